// round 11
// baseline (speedup 1.0000x reference)
#include <cuda_runtime.h>
#include <cuda_fp16.h>
#include <cstdint>

// ---------------- problem constants ----------------
#define N_TOK 8192
#define H     1024
#define E     8
#define IE    512
#define F2    1024
#define VOCAB 32000

// ---------------- scratch ----------------
__device__ int g_expert_ids[N_TOK];
__device__ int g_offsets[E + 1];
__device__ int g_sorted[N_TOK];
__device__ int g_pos[N_TOK];          // token -> sorted position
__device__ int g_tile_expert[96];
__device__ int g_tile_mstart[96];
__device__ int g_num_tiles;

__device__ __half g_xs[(size_t)N_TOK * H];      // sorted order, fp16
__device__ __half g_gup_h[(size_t)E * H * F2];  // fp16 weights
__device__ __half g_dwn_h[(size_t)E * IE * H];
__device__ __half g_inter[(size_t)N_TOK * IE];  // sorted order, fp16

// ---------------- PTX helpers ----------------
__device__ __forceinline__ uint32_t s2u(const void* p) {
    uint32_t a;
    asm("{ .reg .u64 t; cvta.to.shared.u64 t, %1; cvt.u32.u64 %0, t; }"
        : "=r"(a) : "l"(p));
    return a;
}
__device__ __forceinline__ void cp16(uint32_t dst, const void* src) {
    asm volatile("cp.async.ca.shared.global [%0], [%1], 16;"
                 :: "r"(dst), "l"(src) : "memory");
}
__device__ __forceinline__ void cp_commit() {
    asm volatile("cp.async.commit_group;" ::: "memory");
}
__device__ __forceinline__ void cp_wait1() {
    asm volatile("cp.async.wait_group 1;" ::: "memory");
}
__device__ __forceinline__ void ldmx4(uint32_t* r, uint32_t a) {
    asm volatile("ldmatrix.sync.aligned.m8n8.x4.shared.b16 {%0,%1,%2,%3}, [%4];"
                 : "=r"(r[0]), "=r"(r[1]), "=r"(r[2]), "=r"(r[3]) : "r"(a));
}
__device__ __forceinline__ void ldmx4t(uint32_t* r, uint32_t a) {
    asm volatile("ldmatrix.sync.aligned.m8n8.x4.trans.shared.b16 {%0,%1,%2,%3}, [%4];"
                 : "=r"(r[0]), "=r"(r[1]), "=r"(r[2]), "=r"(r[3]) : "r"(a));
}
__device__ __forceinline__ void mma16816(float* d, const uint32_t* a,
                                         const uint32_t* b) {
    asm volatile(
        "mma.sync.aligned.m16n8k16.row.col.f32.f16.f16.f32 "
        "{%0,%1,%2,%3}, {%4,%5,%6,%7}, {%8,%9}, {%0,%1,%2,%3};"
        : "+f"(d[0]), "+f"(d[1]), "+f"(d[2]), "+f"(d[3])
        : "r"(a[0]), "r"(a[1]), "r"(a[2]), "r"(a[3]), "r"(b[0]), "r"(b[1]));
}

// ---------------- smem layout (BK = 64) ----------------
#define BK     64
#define A_ROWB 144   // 64 fp16 (128B) + 16B pad
#define B_ROWB 272   // 128 fp16 (256B) + 16B pad
#define OFF_AH 0
#define OFF_BH 18432
#define STG    35840          // 18432 + 64*272
#define STAGE_BASE 512
#define SMEM_TOT (STAGE_BASE + 3 * STG)   // 108032 (x2 CTA = 216064 <= 228KB)

__device__ __forceinline__ uint32_t a_addr(uint32_t base, int lane, int mbase,
                                           int k16) {
    int row = mbase + (lane & 15);
    return base + row * A_ROWB + k16 * 32 + ((lane >> 4) << 4);
}
__device__ __forceinline__ uint32_t b_addr(uint32_t base, int lane, int nbase,
                                           int k16) {
    int krow = k16 * 16 + (lane & 15);
    return base + krow * B_ROWB + nbase * 2 + ((lane >> 4) << 4);
}

// warp tile 64x64: one k16 step = 8 ldmatrix.x4 + 32 HMMA
__device__ __forceinline__ void compute_k16(uint32_t stg, int lane, int warpM,
                                            int warpN, int k16,
                                            float acc[4][8][4]) {
    uint32_t ah[4][4], bh[4][4];
#pragma unroll
    for (int i = 0; i < 4; i++)
        ldmx4(ah[i], a_addr(stg + OFF_AH, lane, warpM * 64 + i * 16, k16));
#pragma unroll
    for (int j = 0; j < 4; j++)
        ldmx4t(bh[j], b_addr(stg + OFF_BH, lane, warpN * 64 + j * 16, k16));
#pragma unroll
    for (int i = 0; i < 4; i++) {
#pragma unroll
        for (int j = 0; j < 8; j++)
            mma16816(acc[i][j], ah[i], &bh[j >> 1][(j & 1) * 2]);
    }
}

// ---------------- router (no atomics) ----------------
__global__ void k_router(const float* __restrict__ mu, const int* __restrict__ tok,
                         const float* __restrict__ w) {
    __shared__ float ws[E * H];
    int tid = threadIdx.x;
    for (int i = tid; i < E * H; i += 256) ws[i] = w[i];
    __syncthreads();
    int warp = tid >> 5, lane = tid & 31;
    int n = blockIdx.x * 8 + warp;
    const float* mrow = mu + (size_t)n * H;
    float acc[E];
#pragma unroll
    for (int e = 0; e < E; e++) acc[e] = 0.f;
    for (int h = lane; h < H; h += 32) {
        float m = mrow[h];
#pragma unroll
        for (int e = 0; e < E; e++) acc[e] += m * ws[e * H + h];
    }
#pragma unroll
    for (int off = 16; off > 0; off >>= 1)
#pragma unroll
        for (int e = 0; e < E; e++)
            acc[e] += __shfl_down_sync(0xffffffffu, acc[e], off);
    if (lane == 0) {
        int id = tok[n];
        if (id < 0) id = 0;
        if (id >= VOCAB) id = VOCAB - 1;
        int base = id & (E - 1);
        float best = -1e30f;
        int be = 0;
#pragma unroll
        for (int e = 0; e < E; e++) {
            float v = acc[e] + (e == base ? 10.0f : 0.0f);
            if (v > best) { best = v; be = e; }
        }
        g_expert_ids[n] = be;
    }
}

// ---------------- plan + scatter: atomic-free, deterministic ----------------
__global__ void k_plan_scatter() {
    __shared__ int wcnt[8][E];
    __shared__ int wbase[8][E];
    int tid = threadIdx.x, lane = tid & 31, w = tid >> 5;
    const unsigned FULL = 0xffffffffu;

    int cnt = 0;
    for (int it = 0; it < 32; it++) {
        int n = w * 1024 + it * 32 + lane;
        int id = g_expert_ids[n];
#pragma unroll
        for (int e = 0; e < E; e++) {
            unsigned m = __ballot_sync(FULL, id == e);
            if (lane == e) cnt += __popc(m);
        }
    }
    if (lane < E) wcnt[w][lane] = cnt;
    __syncthreads();

    if (tid == 0) {
        int tot[E];
        for (int e = 0; e < E; e++) {
            tot[e] = 0;
            for (int ww = 0; ww < 8; ww++) tot[e] += wcnt[ww][e];
        }
        int off = 0;
        for (int e = 0; e < E; e++) { g_offsets[e] = off; off += tot[e]; }
        g_offsets[E] = off;
        int tt = 0;
        for (int e = 0; e < E; e++)
            for (int ms = 0; ms < tot[e]; ms += 128) {
                g_tile_expert[tt] = e;
                g_tile_mstart[tt] = ms;
                tt++;
            }
        g_num_tiles = tt;
        for (int e = 0; e < E; e++) {
            int b = g_offsets[e];
            for (int ww = 0; ww < 8; ww++) { wbase[ww][e] = b; b += wcnt[ww][e]; }
        }
    }
    __syncthreads();

    int wb = (lane < E) ? wbase[w][lane] : 0;
    for (int it = 0; it < 32; it++) {
        int n = w * 1024 + it * 32 + lane;
        int id = g_expert_ids[n];
        unsigned m = __match_any_sync(FULL, id);
        int rank = __popc(m & ((1u << lane) - 1u));
        int base = __shfl_sync(FULL, wb, id);
        g_sorted[base + rank] = n;
        g_pos[n] = base + rank;
#pragma unroll
        for (int e = 0; e < E; e++) {
            unsigned mm = __ballot_sync(FULL, id == e);
            if (lane == e) wb += __popc(mm);
        }
    }
}

// fp32 -> fp16 convert: gup + dwn + x(sorted via g_pos) in one launch
#define GUP4 (E * H * F2 / 4)    // 2097152
#define DWN4 (E * IE * H / 4)    // 1048576
#define X4   (N_TOK * H / 4)     // 2097152
#define H4   (H / 4)
__global__ void k_cvt3(const float* __restrict__ gup,
                       const float* __restrict__ dwn,
                       const float* __restrict__ x) {
    int i = blockIdx.x * 256 + threadIdx.x;
    const float* in;
    __half* out;
    int iidx, oidx;
    if (i < GUP4) { in = gup; out = g_gup_h; iidx = i; oidx = i; }
    else if (i < GUP4 + DWN4) {
        in = dwn; out = g_dwn_h; iidx = i - GUP4; oidx = iidx;
    } else if (i < GUP4 + DWN4 + X4) {
        in = x; out = g_xs;
        iidx = i - GUP4 - DWN4;
        int n = iidx / H4, c4 = iidx - n * H4;
        oidx = g_pos[n] * H4 + c4;
    } else return;
    float4 v = ((const float4*)in)[iidx];
    __half2 a = __floats2half2_rn(v.x, v.y);
    __half2 b = __floats2half2_rn(v.z, v.w);
    ((uint2*)out)[oidx] = make_uint2(*(uint32_t*)&a, *(uint32_t*)&b);
}

// ---------------- GEMM1 stage load (128 threads, 16 cp16 each) -------------
// B column interleave (32-col groups): [gate(n0g..+31) | up(n0g..+31) |
//                                       gate(n0g+32..+63) | up(n0g+32..+63)]
__device__ __forceinline__ void g1_load(uint32_t sb, int s,
                                        const __half* wh,
                                        int m0, int k0, int n0g, int tid) {
    uint32_t stg = sb + s * STG;
#pragma unroll
    for (int q = 0; q < 8; q++) {
        int t = tid + q * 128;  // 0..1023
        // A: row = t>>3 (0..127), chunk c = t&7 (16B of 128B row)
        int row = t >> 3, c = t & 7;
        int sr = m0 + row;
        if (sr > N_TOK - 1) sr = N_TOK - 1;
        cp16(stg + OFF_AH + row * A_ROWB + c * 16,
             g_xs + (size_t)sr * H + k0 + c * 8);
        // B: krow = t>>4 (0..63), chunk c2 = t&15 (16B = 8 cols)
        int kr = t >> 4, c2 = t & 15;
        int grp = c2 >> 2;                 // 0..3
        int within = (c2 & 3) * 8;
        int col = ((grp & 1) ? IE : 0) + n0g + (grp >> 1) * 32 + within;
        cp16(stg + OFF_BH + kr * B_ROWB + c2 * 16,
             wh + (size_t)(k0 + kr) * F2 + col);
    }
}

__global__ __launch_bounds__(128, 2) void k_gemm1_mma() {
    int t = blockIdx.x;
    if (t >= g_num_tiles) return;
    int e = g_tile_expert[t];
    int m0 = g_offsets[e] + g_tile_mstart[t];
    int rows = g_offsets[e + 1] - m0;
    if (rows > 128) rows = 128;
    int n0g = blockIdx.y * 64;

    extern __shared__ char smraw[];
    uint32_t sb = s2u(smraw) + STAGE_BASE;
    int tid = threadIdx.x;

    const __half* wh = g_gup_h + (size_t)e * H * F2;

    g1_load(sb, 0, wh, m0, 0, n0g, tid);
    cp_commit();
    g1_load(sb, 1, wh, m0, BK, n0g, tid);
    cp_commit();

    float acc[4][8][4];
#pragma unroll
    for (int i = 0; i < 4; i++)
#pragma unroll
        for (int j = 0; j < 8; j++)
#pragma unroll
            for (int r = 0; r < 4; r++) acc[i][j][r] = 0.f;

    int lane = tid & 31, w = tid >> 5;
    int warpM = w >> 1, warpN = w & 1;   // 2M x 2N, warp tile 64x64

    const int NS = H / BK;  // 16
    for (int ki = 0; ki < NS; ki++) {
        cp_wait1();
        __syncthreads();
        if (ki + 2 < NS)
            g1_load(sb, (ki + 2) % 3, wh, m0, (ki + 2) * BK, n0g, tid);
        cp_commit();
        uint32_t stg = sb + (ki % 3) * STG;
#pragma unroll
        for (int k16 = 0; k16 < 4; k16++)
            compute_k16(stg, lane, warpM, warpN, k16, acc);
    }

    // epilogue: j=0..3 gate, j+4 up; inter col = n0g + warpN*32 + j*8
#pragma unroll
    for (int i = 0; i < 4; i++) {
        int r0 = warpM * 64 + i * 16 + (lane >> 2);
#pragma unroll
        for (int j = 0; j < 4; j++) {
            int col = n0g + warpN * 32 + j * 8 + (lane & 3) * 2;
#pragma unroll
            for (int hfa = 0; hfa < 2; hfa++) {
                int m = r0 + hfa * 8;
                if (m < rows) {
                    float g0 = acc[i][j][hfa * 2 + 0];
                    float g1 = acc[i][j][hfa * 2 + 1];
                    float u0 = acc[i][j + 4][hfa * 2 + 0];
                    float u1 = acc[i][j + 4][hfa * 2 + 1];
                    float v0 = g0 / (1.f + __expf(-g0)) * u0;
                    float v1 = g1 / (1.f + __expf(-g1)) * u1;
                    __half2 hv = __floats2half2_rn(v0, v1);
                    ((uint32_t*)g_inter)[((size_t)(m0 + m) * IE + col) >> 1] =
                        *(uint32_t*)&hv;
                }
            }
        }
    }
}

// ---------------- GEMM2 ----------------
__device__ __forceinline__ void g2_load(uint32_t sb, int s,
                                        const __half* wh,
                                        int m0, int k0, int n0, int tid) {
    uint32_t stg = sb + s * STG;
#pragma unroll
    for (int q = 0; q < 8; q++) {
        int t = tid + q * 128;
        int row = t >> 3, c = t & 7;
        int sr = m0 + row;
        if (sr > N_TOK - 1) sr = N_TOK - 1;
        cp16(stg + OFF_AH + row * A_ROWB + c * 16,
             g_inter + (size_t)sr * IE + k0 + c * 8);
        int kr = t >> 4, c2 = t & 15;
        cp16(stg + OFF_BH + kr * B_ROWB + c2 * 16,
             wh + (size_t)(k0 + kr) * H + n0 + c2 * 8);
    }
}

__global__ __launch_bounds__(128, 2) void k_gemm2_mma(float* __restrict__ out) {
    int t = blockIdx.x;
    if (t >= g_num_tiles) return;
    int e = g_tile_expert[t];
    int m0 = g_offsets[e] + g_tile_mstart[t];
    int rows = g_offsets[e + 1] - m0;
    if (rows > 128) rows = 128;
    int n0 = blockIdx.y * 128;

    extern __shared__ char smraw[];
    int* sRow = (int*)smraw;
    uint32_t sb = s2u(smraw) + STAGE_BASE;
    int tid = threadIdx.x;
    if (tid < 128) sRow[tid] = (tid < rows) ? g_sorted[m0 + tid] : -1;
    __syncthreads();

    const __half* wh = g_dwn_h + (size_t)e * IE * H;

    g2_load(sb, 0, wh, m0, 0, n0, tid);
    cp_commit();
    g2_load(sb, 1, wh, m0, BK, n0, tid);
    cp_commit();

    float acc[4][8][4];
#pragma unroll
    for (int i = 0; i < 4; i++)
#pragma unroll
        for (int j = 0; j < 8; j++)
#pragma unroll
            for (int r = 0; r < 4; r++) acc[i][j][r] = 0.f;

    int lane = tid & 31, w = tid >> 5;
    int warpM = w >> 1, warpN = w & 1;

    const int NS = IE / BK;  // 8
    for (int ki = 0; ki < NS; ki++) {
        cp_wait1();
        __syncthreads();
        if (ki + 2 < NS) g2_load(sb, (ki + 2) % 3, wh, m0, (ki + 2) * BK, n0, tid);
        cp_commit();
        uint32_t stg = sb + (ki % 3) * STG;
#pragma unroll
        for (int k16 = 0; k16 < 4; k16++)
            compute_k16(stg, lane, warpM, warpN, k16, acc);
    }

#pragma unroll
    for (int i = 0; i < 4; i++) {
        int r0 = warpM * 64 + i * 16 + (lane >> 2);
#pragma unroll
        for (int hfa = 0; hfa < 2; hfa++) {
            int m = r0 + hfa * 8;
            if (m < rows) {
                int token = sRow[m];
                float* po = out + (size_t)token * H + n0 + warpN * 64;
#pragma unroll
                for (int j = 0; j < 8; j++) {
                    int col = j * 8 + (lane & 3) * 2;
                    *(float2*)(po + col) =
                        make_float2(acc[i][j][hfa * 2 + 0], acc[i][j][hfa * 2 + 1]);
                }
            }
        }
    }
}

// ---------------- launch ----------------
extern "C" void kernel_launch(void* const* d_in, const int* in_sizes, int n_in,
                              void* d_out, int out_size) {
    const float* hs  = (const float*)d_in[0];
    const int*   tok = (const int*)d_in[1];
    const float* mu  = (const float*)d_in[2];
    const float* gup = (const float*)d_in[3];
    const float* dwn = (const float*)d_in[4];
    const float* rw  = (const float*)d_in[5];
    float* out = (float*)d_out;
    (void)in_sizes; (void)n_in; (void)out_size;

    cudaFuncSetAttribute(k_gemm1_mma, cudaFuncAttributeMaxDynamicSharedMemorySize,
                         SMEM_TOT);
    cudaFuncSetAttribute(k_gemm2_mma, cudaFuncAttributeMaxDynamicSharedMemorySize,
                         SMEM_TOT);

    k_router<<<N_TOK / 8, 256>>>(mu, tok, rw);
    k_plan_scatter<<<1, 256>>>();
    k_cvt3<<<(GUP4 + DWN4 + X4) / 256, 256>>>(gup, dwn, hs);

    k_gemm1_mma<<<dim3(72, 8), 128, SMEM_TOT>>>();
    k_gemm2_mma<<<dim3(72, 8), 128, SMEM_TOT>>>(out);
}

// round 12
// speedup vs baseline: 1.1104x; 1.1104x over previous
#include <cuda_runtime.h>
#include <cuda_fp16.h>
#include <cstdint>

// ---------------- problem constants ----------------
#define N_TOK 8192
#define H     1024
#define E     8
#define IE    512
#define F2    1024
#define VOCAB 32000

// ---------------- scratch ----------------
__device__ int g_expert_ids[N_TOK];
__device__ int g_offsets[E + 1];
__device__ int g_sorted[N_TOK];
__device__ int g_pos[N_TOK];          // token -> sorted position
__device__ int g_tile_expert[96];
__device__ int g_tile_mstart[96];
__device__ int g_num_tiles;

__device__ __half g_xs[(size_t)N_TOK * H];      // sorted order, fp16
__device__ __half g_gup_h[(size_t)E * H * F2];  // fp16 weights
__device__ __half g_dwn_h[(size_t)E * IE * H];
__device__ __half g_inter[(size_t)N_TOK * IE];  // sorted order, fp16

// ---------------- PTX helpers ----------------
__device__ __forceinline__ uint32_t s2u(const void* p) {
    uint32_t a;
    asm("{ .reg .u64 t; cvta.to.shared.u64 t, %1; cvt.u32.u64 %0, t; }"
        : "=r"(a) : "l"(p));
    return a;
}
// .cg: bypass L1 (L2-only) — keeps staging traffic off the contended L1 pipe
__device__ __forceinline__ void cp16(uint32_t dst, const void* src) {
    asm volatile("cp.async.cg.shared.global [%0], [%1], 16;"
                 :: "r"(dst), "l"(src) : "memory");
}
__device__ __forceinline__ void cp_commit() {
    asm volatile("cp.async.commit_group;" ::: "memory");
}
__device__ __forceinline__ void cp_wait1() {
    asm volatile("cp.async.wait_group 1;" ::: "memory");
}
__device__ __forceinline__ void ldmx4(uint32_t* r, uint32_t a) {
    asm volatile("ldmatrix.sync.aligned.m8n8.x4.shared.b16 {%0,%1,%2,%3}, [%4];"
                 : "=r"(r[0]), "=r"(r[1]), "=r"(r[2]), "=r"(r[3]) : "r"(a));
}
__device__ __forceinline__ void ldmx4t(uint32_t* r, uint32_t a) {
    asm volatile("ldmatrix.sync.aligned.m8n8.x4.trans.shared.b16 {%0,%1,%2,%3}, [%4];"
                 : "=r"(r[0]), "=r"(r[1]), "=r"(r[2]), "=r"(r[3]) : "r"(a));
}
__device__ __forceinline__ void mma16816(float* d, const uint32_t* a,
                                         const uint32_t* b) {
    asm volatile(
        "mma.sync.aligned.m16n8k16.row.col.f32.f16.f16.f32 "
        "{%0,%1,%2,%3}, {%4,%5,%6,%7}, {%8,%9}, {%0,%1,%2,%3};"
        : "+f"(d[0]), "+f"(d[1]), "+f"(d[2]), "+f"(d[3])
        : "r"(a[0]), "r"(a[1]), "r"(a[2]), "r"(a[3]), "r"(b[0]), "r"(b[1]));
}

// ---------------- smem layout (BK = 64) ----------------
#define BK     64
#define A_ROWB 144   // 64 fp16 (128B) + 16B pad
#define B_ROWB 272   // 128 fp16 (256B) + 16B pad
#define OFF_AH 0
#define OFF_BH 18432
#define STG    35840          // 18432 + 64*272
#define STAGE_BASE 512
#define SMEM_TOT (STAGE_BASE + 3 * STG)   // 108032 (x2 CTA = 216064 <= 228KB)

__device__ __forceinline__ uint32_t a_addr(uint32_t base, int lane, int mbase,
                                           int k16) {
    int row = mbase + (lane & 15);
    return base + row * A_ROWB + k16 * 32 + ((lane >> 4) << 4);
}
__device__ __forceinline__ uint32_t b_addr(uint32_t base, int lane, int nbase,
                                           int k16) {
    int krow = k16 * 16 + (lane & 15);
    return base + krow * B_ROWB + nbase * 2 + ((lane >> 4) << 4);
}

// warp tile 64x32: one k16 step = 6 ldmatrix.x4 + 16 HMMA
__device__ __forceinline__ void compute_k16(uint32_t stg, int lane, int warpM,
                                            int p0, int p1, int k16,
                                            float acc[4][4][4]) {
    uint32_t ah[4][4], bh[2][4];
#pragma unroll
    for (int i = 0; i < 4; i++)
        ldmx4(ah[i], a_addr(stg + OFF_AH, lane, warpM * 64 + i * 16, k16));
    ldmx4t(bh[0], b_addr(stg + OFF_BH, lane, p0, k16));
    ldmx4t(bh[1], b_addr(stg + OFF_BH, lane, p1, k16));
#pragma unroll
    for (int i = 0; i < 4; i++) {
#pragma unroll
        for (int j = 0; j < 4; j++)
            mma16816(acc[i][j], ah[i], &bh[j >> 1][(j & 1) * 2]);
    }
}

// ---------------- router (no atomics) ----------------
__global__ void k_router(const float* __restrict__ mu, const int* __restrict__ tok,
                         const float* __restrict__ w) {
    __shared__ float ws[E * H];
    int tid = threadIdx.x;
    for (int i = tid; i < E * H; i += 256) ws[i] = w[i];
    __syncthreads();
    int warp = tid >> 5, lane = tid & 31;
    int n = blockIdx.x * 8 + warp;
    const float* mrow = mu + (size_t)n * H;
    float acc[E];
#pragma unroll
    for (int e = 0; e < E; e++) acc[e] = 0.f;
    for (int h = lane; h < H; h += 32) {
        float m = mrow[h];
#pragma unroll
        for (int e = 0; e < E; e++) acc[e] += m * ws[e * H + h];
    }
#pragma unroll
    for (int off = 16; off > 0; off >>= 1)
#pragma unroll
        for (int e = 0; e < E; e++)
            acc[e] += __shfl_down_sync(0xffffffffu, acc[e], off);
    if (lane == 0) {
        int id = tok[n];
        if (id < 0) id = 0;
        if (id >= VOCAB) id = VOCAB - 1;
        int base = id & (E - 1);
        float best = -1e30f;
        int be = 0;
#pragma unroll
        for (int e = 0; e < E; e++) {
            float v = acc[e] + (e == base ? 10.0f : 0.0f);
            if (v > best) { best = v; be = e; }
        }
        g_expert_ids[n] = be;
    }
}

// ---------------- plan + scatter: atomic-free, deterministic ----------------
__global__ void k_plan_scatter() {
    __shared__ int wcnt[8][E];
    __shared__ int wbase[8][E];
    int tid = threadIdx.x, lane = tid & 31, w = tid >> 5;
    const unsigned FULL = 0xffffffffu;

    int cnt = 0;
    for (int it = 0; it < 32; it++) {
        int n = w * 1024 + it * 32 + lane;
        int id = g_expert_ids[n];
#pragma unroll
        for (int e = 0; e < E; e++) {
            unsigned m = __ballot_sync(FULL, id == e);
            if (lane == e) cnt += __popc(m);
        }
    }
    if (lane < E) wcnt[w][lane] = cnt;
    __syncthreads();

    if (tid == 0) {
        int tot[E];
        for (int e = 0; e < E; e++) {
            tot[e] = 0;
            for (int ww = 0; ww < 8; ww++) tot[e] += wcnt[ww][e];
        }
        int off = 0;
        for (int e = 0; e < E; e++) { g_offsets[e] = off; off += tot[e]; }
        g_offsets[E] = off;
        int tt = 0;
        for (int e = 0; e < E; e++)
            for (int ms = 0; ms < tot[e]; ms += 128) {
                g_tile_expert[tt] = e;
                g_tile_mstart[tt] = ms;
                tt++;
            }
        g_num_tiles = tt;
        for (int e = 0; e < E; e++) {
            int b = g_offsets[e];
            for (int ww = 0; ww < 8; ww++) { wbase[ww][e] = b; b += wcnt[ww][e]; }
        }
    }
    __syncthreads();

    int wb = (lane < E) ? wbase[w][lane] : 0;
    for (int it = 0; it < 32; it++) {
        int n = w * 1024 + it * 32 + lane;
        int id = g_expert_ids[n];
        unsigned m = __match_any_sync(FULL, id);
        int rank = __popc(m & ((1u << lane) - 1u));
        int base = __shfl_sync(FULL, wb, id);
        g_sorted[base + rank] = n;
        g_pos[n] = base + rank;
#pragma unroll
        for (int e = 0; e < E; e++) {
            unsigned mm = __ballot_sync(FULL, id == e);
            if (lane == e) wb += __popc(mm);
        }
    }
}

// fp32 -> fp16 convert: gup + dwn + x(written into sorted order) in one launch
#define GUP4 (E * H * F2 / 4)    // 2097152
#define DWN4 (E * IE * H / 4)    // 1048576
#define X4   (N_TOK * H / 4)     // 2097152
#define H4   (H / 4)
__global__ void k_cvt3(const float* __restrict__ gup,
                       const float* __restrict__ dwn,
                       const float* __restrict__ x) {
    int i = blockIdx.x * 256 + threadIdx.x;
    const float* in;
    __half* out;
    int iidx, oidx;
    if (i < GUP4) { in = gup; out = g_gup_h; iidx = i; oidx = i; }
    else if (i < GUP4 + DWN4) {
        in = dwn; out = g_dwn_h; iidx = i - GUP4; oidx = iidx;
    } else if (i < GUP4 + DWN4 + X4) {
        in = x; out = g_xs;
        iidx = i - GUP4 - DWN4;
        int n = iidx / H4, c4 = iidx - n * H4;
        oidx = g_pos[n] * H4 + c4;
    } else return;
    float4 v = ((const float4*)in)[iidx];
    __half2 a = __floats2half2_rn(v.x, v.y);
    __half2 b = __floats2half2_rn(v.z, v.w);
    ((uint2*)out)[oidx] = make_uint2(*(uint32_t*)&a, *(uint32_t*)&b);
}

// ---------------- GEMM1 stage load (256 threads, 8 cp16 each) --------------
__device__ __forceinline__ void g1_load(uint32_t sb, int s,
                                        const __half* wh,
                                        int m0, int k0, int n0g, int tid) {
    uint32_t stg = sb + s * STG;
#pragma unroll
    for (int q = 0; q < 4; q++) {
        int t = tid + q * 256;  // 0..1023
        // A: row = t>>3 (0..127), chunk c = t&7 (16B of 128B row)
        int row = t >> 3, c = t & 7;
        int sr = m0 + row;
        if (sr > N_TOK - 1) sr = N_TOK - 1;
        cp16(stg + OFF_AH + row * A_ROWB + c * 16,
             g_xs + (size_t)sr * H + k0 + c * 8);
        // B: krow = t>>4 (0..63), chunk c2 = t&15 (16B of 256B row)
        int kr = t >> 4, c2 = t & 15;
        int col = (c2 < 8) ? (n0g + c2 * 8) : (IE + n0g + (c2 - 8) * 8);
        cp16(stg + OFF_BH + kr * B_ROWB + c2 * 16,
             wh + (size_t)(k0 + kr) * F2 + col);
    }
}

__global__ __launch_bounds__(256, 2) void k_gemm1_mma() {
    int t = blockIdx.x;
    if (t >= g_num_tiles) return;
    int e = g_tile_expert[t];
    int m0 = g_offsets[e] + g_tile_mstart[t];
    int rows = g_offsets[e + 1] - m0;
    if (rows > 128) rows = 128;
    int n0g = blockIdx.y * 64;

    extern __shared__ char smraw[];
    uint32_t sb = s2u(smraw) + STAGE_BASE;
    int tid = threadIdx.x;

    const __half* wh = g_gup_h + (size_t)e * H * F2;

    g1_load(sb, 0, wh, m0, 0, n0g, tid);
    cp_commit();
    g1_load(sb, 1, wh, m0, BK, n0g, tid);
    cp_commit();

    float acc[4][4][4];
#pragma unroll
    for (int i = 0; i < 4; i++)
#pragma unroll
        for (int j = 0; j < 4; j++)
#pragma unroll
            for (int r = 0; r < 4; r++) acc[i][j][r] = 0.f;

    int lane = tid & 31, w = tid >> 5;
    int warpM = w >> 2, warpN = w & 3;          // 2M x 4N
    int p0 = warpN * 16, p1 = 64 + warpN * 16;  // gate / up halves

    const int NS = H / BK;  // 16
    for (int ki = 0; ki < NS; ki++) {
        cp_wait1();
        __syncthreads();
        if (ki + 2 < NS)
            g1_load(sb, (ki + 2) % 3, wh, m0, (ki + 2) * BK, n0g, tid);
        cp_commit();
        uint32_t stg = sb + (ki % 3) * STG;
#pragma unroll
        for (int k16 = 0; k16 < 4; k16++)
            compute_k16(stg, lane, warpM, p0, p1, k16, acc);
    }

    // epilogue: j=0,1 gate; j+2 up (same inter cols)
#pragma unroll
    for (int i = 0; i < 4; i++) {
        int r0 = warpM * 64 + i * 16 + (lane >> 2);
#pragma unroll
        for (int j = 0; j < 2; j++) {
            int col = n0g + warpN * 16 + j * 8 + (lane & 3) * 2;
#pragma unroll
            for (int hfa = 0; hfa < 2; hfa++) {
                int m = r0 + hfa * 8;
                if (m < rows) {
                    float g0 = acc[i][j][hfa * 2 + 0];
                    float g1 = acc[i][j][hfa * 2 + 1];
                    float u0 = acc[i][j + 2][hfa * 2 + 0];
                    float u1 = acc[i][j + 2][hfa * 2 + 1];
                    float v0 = g0 / (1.f + __expf(-g0)) * u0;
                    float v1 = g1 / (1.f + __expf(-g1)) * u1;
                    __half2 hv = __floats2half2_rn(v0, v1);
                    ((uint32_t*)g_inter)[((size_t)(m0 + m) * IE + col) >> 1] =
                        *(uint32_t*)&hv;
                }
            }
        }
    }
}

// ---------------- GEMM2 ----------------
__device__ __forceinline__ void g2_load(uint32_t sb, int s,
                                        const __half* wh,
                                        int m0, int k0, int n0, int tid) {
    uint32_t stg = sb + s * STG;
#pragma unroll
    for (int q = 0; q < 4; q++) {
        int t = tid + q * 256;
        int row = t >> 3, c = t & 7;
        int sr = m0 + row;
        if (sr > N_TOK - 1) sr = N_TOK - 1;
        cp16(stg + OFF_AH + row * A_ROWB + c * 16,
             g_inter + (size_t)sr * IE + k0 + c * 8);
        int kr = t >> 4, c2 = t & 15;
        cp16(stg + OFF_BH + kr * B_ROWB + c2 * 16,
             wh + (size_t)(k0 + kr) * H + n0 + c2 * 8);
    }
}

__global__ __launch_bounds__(256, 2) void k_gemm2_mma(float* __restrict__ out) {
    int t = blockIdx.x;
    if (t >= g_num_tiles) return;
    int e = g_tile_expert[t];
    int m0 = g_offsets[e] + g_tile_mstart[t];
    int rows = g_offsets[e + 1] - m0;
    if (rows > 128) rows = 128;
    int n0 = blockIdx.y * 128;

    extern __shared__ char smraw[];
    int* sRow = (int*)smraw;
    uint32_t sb = s2u(smraw) + STAGE_BASE;
    int tid = threadIdx.x;
    if (tid < 128) sRow[tid] = (tid < rows) ? g_sorted[m0 + tid] : -1;
    __syncthreads();

    const __half* wh = g_dwn_h + (size_t)e * IE * H;

    g2_load(sb, 0, wh, m0, 0, n0, tid);
    cp_commit();
    g2_load(sb, 1, wh, m0, BK, n0, tid);
    cp_commit();

    float acc[4][4][4];
#pragma unroll
    for (int i = 0; i < 4; i++)
#pragma unroll
        for (int j = 0; j < 4; j++)
#pragma unroll
            for (int r = 0; r < 4; r++) acc[i][j][r] = 0.f;

    int lane = tid & 31, w = tid >> 5;
    int warpM = w >> 2, warpN = w & 3;
    int p0 = warpN * 32, p1 = warpN * 32 + 16;

    const int NS = IE / BK;  // 8
    for (int ki = 0; ki < NS; ki++) {
        cp_wait1();
        __syncthreads();
        if (ki + 2 < NS) g2_load(sb, (ki + 2) % 3, wh, m0, (ki + 2) * BK, n0, tid);
        cp_commit();
        uint32_t stg = sb + (ki % 3) * STG;
#pragma unroll
        for (int k16 = 0; k16 < 4; k16++)
            compute_k16(stg, lane, warpM, p0, p1, k16, acc);
    }

#pragma unroll
    for (int i = 0; i < 4; i++) {
        int r0 = warpM * 64 + i * 16 + (lane >> 2);
#pragma unroll
        for (int hfa = 0; hfa < 2; hfa++) {
            int m = r0 + hfa * 8;
            if (m < rows) {
                int token = sRow[m];
                float* po = out + (size_t)token * H + n0;
#pragma unroll
                for (int j = 0; j < 4; j++) {
                    int col = warpN * 32 + j * 8 + (lane & 3) * 2;
                    *(float2*)(po + col) =
                        make_float2(acc[i][j][hfa * 2 + 0], acc[i][j][hfa * 2 + 1]);
                }
            }
        }
    }
}

// ---------------- launch ----------------
extern "C" void kernel_launch(void* const* d_in, const int* in_sizes, int n_in,
                              void* d_out, int out_size) {
    const float* hs  = (const float*)d_in[0];
    const int*   tok = (const int*)d_in[1];
    const float* mu  = (const float*)d_in[2];
    const float* gup = (const float*)d_in[3];
    const float* dwn = (const float*)d_in[4];
    const float* rw  = (const float*)d_in[5];
    float* out = (float*)d_out;
    (void)in_sizes; (void)n_in; (void)out_size;

    cudaFuncSetAttribute(k_gemm1_mma, cudaFuncAttributeMaxDynamicSharedMemorySize,
                         SMEM_TOT);
    cudaFuncSetAttribute(k_gemm2_mma, cudaFuncAttributeMaxDynamicSharedMemorySize,
                         SMEM_TOT);

    k_router<<<N_TOK / 8, 256>>>(mu, tok, rw);
    k_plan_scatter<<<1, 256>>>();
    k_cvt3<<<(GUP4 + DWN4 + X4) / 256, 256>>>(gup, dwn, hs);

    k_gemm1_mma<<<dim3(72, 8), 256, SMEM_TOT>>>();
    k_gemm2_mma<<<dim3(72, 8), 256, SMEM_TOT>>>(out);
}

// round 13
// speedup vs baseline: 1.1629x; 1.0473x over previous
#include <cuda_runtime.h>
#include <cuda_fp16.h>
#include <cstdint>

// ---------------- problem constants ----------------
#define N_TOK 8192
#define H     1024
#define E     8
#define IE    512
#define F2    1024
#define VOCAB 32000

// ---------------- scratch ----------------
__device__ int g_expert_ids[N_TOK];
__device__ int g_counts[E];      // zero-init; k_plan re-zeros after use
__device__ int g_cursor[E];
__device__ int g_offsets[E + 1];
__device__ int g_sorted[N_TOK];
__device__ int g_pos[N_TOK];     // token -> sorted position
__device__ int g_tile_expert[96];
__device__ int g_tile_mstart[96];
__device__ int g_num_tiles;

__device__ __half g_xs[(size_t)N_TOK * H];      // sorted order, fp16
__device__ __half g_gup_h[(size_t)E * H * F2];  // fp16 weights
__device__ __half g_dwn_h[(size_t)E * IE * H];
__device__ __half g_inter[(size_t)N_TOK * IE];  // sorted order, fp16

// ---------------- PTX helpers ----------------
__device__ __forceinline__ uint32_t s2u(const void* p) {
    uint32_t a;
    asm("{ .reg .u64 t; cvta.to.shared.u64 t, %1; cvt.u32.u64 %0, t; }"
        : "=r"(a) : "l"(p));
    return a;
}
// .cg: bypass L1 (L2-only) — keeps staging traffic off the contended L1 pipe
__device__ __forceinline__ void cp16(uint32_t dst, const void* src) {
    asm volatile("cp.async.cg.shared.global [%0], [%1], 16;"
                 :: "r"(dst), "l"(src) : "memory");
}
__device__ __forceinline__ void cp_commit() {
    asm volatile("cp.async.commit_group;" ::: "memory");
}
__device__ __forceinline__ void cp_wait1() {
    asm volatile("cp.async.wait_group 1;" ::: "memory");
}
__device__ __forceinline__ void ldmx4(uint32_t* r, uint32_t a) {
    asm volatile("ldmatrix.sync.aligned.m8n8.x4.shared.b16 {%0,%1,%2,%3}, [%4];"
                 : "=r"(r[0]), "=r"(r[1]), "=r"(r[2]), "=r"(r[3]) : "r"(a));
}
__device__ __forceinline__ void ldmx4t(uint32_t* r, uint32_t a) {
    asm volatile("ldmatrix.sync.aligned.m8n8.x4.trans.shared.b16 {%0,%1,%2,%3}, [%4];"
                 : "=r"(r[0]), "=r"(r[1]), "=r"(r[2]), "=r"(r[3]) : "r"(a));
}
__device__ __forceinline__ void mma16816(float* d, const uint32_t* a,
                                         const uint32_t* b) {
    asm volatile(
        "mma.sync.aligned.m16n8k16.row.col.f32.f16.f16.f32 "
        "{%0,%1,%2,%3}, {%4,%5,%6,%7}, {%8,%9}, {%0,%1,%2,%3};"
        : "+f"(d[0]), "+f"(d[1]), "+f"(d[2]), "+f"(d[3])
        : "r"(a[0]), "r"(a[1]), "r"(a[2]), "r"(a[3]), "r"(b[0]), "r"(b[1]));
}

// ---------------- smem layout (BK = 64) ----------------
#define BK     64
#define A_ROWB 144   // 64 fp16 (128B) + 16B pad
#define B_ROWB 272   // 128 fp16 (256B) + 16B pad
#define OFF_AH 0
#define OFF_BH 18432
#define STG    35840          // 18432 + 64*272
#define STAGE_BASE 512
#define SMEM_TOT (STAGE_BASE + 3 * STG)   // 108032 (x2 CTA = 216064 <= 228KB)

__device__ __forceinline__ uint32_t a_addr(uint32_t base, int lane, int mbase,
                                           int k16) {
    int row = mbase + (lane & 15);
    return base + row * A_ROWB + k16 * 32 + ((lane >> 4) << 4);
}
__device__ __forceinline__ uint32_t b_addr(uint32_t base, int lane, int nbase,
                                           int k16) {
    int krow = k16 * 16 + (lane & 15);
    return base + krow * B_ROWB + nbase * 2 + ((lane >> 4) << 4);
}

// warp tile 64x32: one k16 step = 6 ldmatrix.x4 + 16 HMMA
__device__ __forceinline__ void compute_k16(uint32_t stg, int lane, int warpM,
                                            int p0, int p1, int k16,
                                            float acc[4][4][4]) {
    uint32_t ah[4][4], bh[2][4];
#pragma unroll
    for (int i = 0; i < 4; i++)
        ldmx4(ah[i], a_addr(stg + OFF_AH, lane, warpM * 64 + i * 16, k16));
    ldmx4t(bh[0], b_addr(stg + OFF_BH, lane, p0, k16));
    ldmx4t(bh[1], b_addr(stg + OFF_BH, lane, p1, k16));
#pragma unroll
    for (int i = 0; i < 4; i++) {
#pragma unroll
        for (int j = 0; j < 4; j++)
            mma16816(acc[i][j], ah[i], &bh[j >> 1][(j & 1) * 2]);
    }
}

// ---------------- router (+ smem histogram) ----------------
__global__ void k_router(const float* __restrict__ mu, const int* __restrict__ tok,
                         const float* __restrict__ w) {
    __shared__ float ws[E * H];
    __shared__ int hist[E];
    int tid = threadIdx.x;
    if (tid < E) hist[tid] = 0;
    for (int i = tid; i < E * H; i += 256) ws[i] = w[i];
    __syncthreads();
    int warp = tid >> 5, lane = tid & 31;
    int n = blockIdx.x * 8 + warp;
    const float* mrow = mu + (size_t)n * H;
    float acc[E];
#pragma unroll
    for (int e = 0; e < E; e++) acc[e] = 0.f;
    for (int h = lane; h < H; h += 32) {
        float m = mrow[h];
#pragma unroll
        for (int e = 0; e < E; e++) acc[e] += m * ws[e * H + h];
    }
#pragma unroll
    for (int off = 16; off > 0; off >>= 1)
#pragma unroll
        for (int e = 0; e < E; e++)
            acc[e] += __shfl_down_sync(0xffffffffu, acc[e], off);
    if (lane == 0) {
        int id = tok[n];
        if (id < 0) id = 0;
        if (id >= VOCAB) id = VOCAB - 1;
        int base = id & (E - 1);
        float best = -1e30f;
        int be = 0;
#pragma unroll
        for (int e = 0; e < E; e++) {
            float v = acc[e] + (e == base ? 10.0f : 0.0f);
            if (v > best) { best = v; be = e; }
        }
        g_expert_ids[n] = be;
        atomicAdd(&hist[be], 1);
    }
    __syncthreads();
    if (tid < E && hist[tid] > 0) atomicAdd(&g_counts[tid], hist[tid]);
}

// ---------------- plan: prefix + tile table + cursor init -------------------
__global__ void k_plan() {
    if (threadIdx.x == 0) {
        int off = 0;
        for (int e = 0; e < E; e++) {
            g_offsets[e] = off;
            g_cursor[e] = off;
            off += g_counts[e];
        }
        g_offsets[E] = off;
        int tt = 0;
        for (int e = 0; e < E; e++) {
            int cnt = g_counts[e];
            for (int ms = 0; ms < cnt; ms += 128) {
                g_tile_expert[tt] = e;
                g_tile_mstart[tt] = ms;
                tt++;
            }
        }
        g_num_tiles = tt;
        for (int e = 0; e < E; e++) g_counts[e] = 0;  // clean for replay
    }
}

// ---------------- scatter (atomic; order-independent outputs) --------------
__global__ void k_scatter() {
    int n = blockIdx.x * 256 + threadIdx.x;
    if (n < N_TOK) {
        int e = g_expert_ids[n];
        int p = atomicAdd(&g_cursor[e], 1);
        g_sorted[p] = n;
        g_pos[n] = p;
    }
}

// fp32 -> fp16: gup + dwn + x(sorted via g_pos); 4 float4 per thread (ILP)
#define GUP4 (E * H * F2 / 4)    // 2097152
#define DWN4 (E * IE * H / 4)    // 1048576
#define X4   (N_TOK * H / 4)     // 2097152
#define H4   (H / 4)
__global__ void k_cvt3(const float* __restrict__ gup,
                       const float* __restrict__ dwn,
                       const float* __restrict__ x) {
    int t = blockIdx.x * 256 + threadIdx.x;
    int i0 = t * 4;  // 4 consecutive float4 indices; same region & same x-row
    const float* in;
    __half* out;
    int iidx, oidx;
    if (i0 < GUP4) { in = gup; out = g_gup_h; iidx = i0; oidx = i0; }
    else if (i0 < GUP4 + DWN4) {
        in = dwn; out = g_dwn_h; iidx = i0 - GUP4; oidx = iidx;
    } else if (i0 < GUP4 + DWN4 + X4) {
        in = x; out = g_xs;
        iidx = i0 - GUP4 - DWN4;
        int n = iidx / H4, c4 = iidx - n * H4;
        oidx = g_pos[n] * H4 + c4;
    } else return;
    float4 v0 = ((const float4*)in)[iidx + 0];
    float4 v1 = ((const float4*)in)[iidx + 1];
    float4 v2 = ((const float4*)in)[iidx + 2];
    float4 v3 = ((const float4*)in)[iidx + 3];
    uint2* o = (uint2*)out + oidx;
    __half2 a, b;
    a = __floats2half2_rn(v0.x, v0.y); b = __floats2half2_rn(v0.z, v0.w);
    o[0] = make_uint2(*(uint32_t*)&a, *(uint32_t*)&b);
    a = __floats2half2_rn(v1.x, v1.y); b = __floats2half2_rn(v1.z, v1.w);
    o[1] = make_uint2(*(uint32_t*)&a, *(uint32_t*)&b);
    a = __floats2half2_rn(v2.x, v2.y); b = __floats2half2_rn(v2.z, v2.w);
    o[2] = make_uint2(*(uint32_t*)&a, *(uint32_t*)&b);
    a = __floats2half2_rn(v3.x, v3.y); b = __floats2half2_rn(v3.z, v3.w);
    o[3] = make_uint2(*(uint32_t*)&a, *(uint32_t*)&b);
}

// ---------------- GEMM1 stage load (256 threads, 8 cp16 each) --------------
__device__ __forceinline__ void g1_load(uint32_t sb, int s,
                                        const __half* wh,
                                        int m0, int k0, int n0g, int tid) {
    uint32_t stg = sb + s * STG;
#pragma unroll
    for (int q = 0; q < 4; q++) {
        int t = tid + q * 256;  // 0..1023
        int row = t >> 3, c = t & 7;
        int sr = m0 + row;
        if (sr > N_TOK - 1) sr = N_TOK - 1;
        cp16(stg + OFF_AH + row * A_ROWB + c * 16,
             g_xs + (size_t)sr * H + k0 + c * 8);
        int kr = t >> 4, c2 = t & 15;
        int col = (c2 < 8) ? (n0g + c2 * 8) : (IE + n0g + (c2 - 8) * 8);
        cp16(stg + OFF_BH + kr * B_ROWB + c2 * 16,
             wh + (size_t)(k0 + kr) * F2 + col);
    }
}

__global__ __launch_bounds__(256, 2) void k_gemm1_mma() {
    int t = blockIdx.x;
    if (t >= g_num_tiles) return;
    int e = g_tile_expert[t];
    int m0 = g_offsets[e] + g_tile_mstart[t];
    int rows = g_offsets[e + 1] - m0;
    if (rows > 128) rows = 128;
    int n0g = blockIdx.y * 64;

    extern __shared__ char smraw[];
    uint32_t sb = s2u(smraw) + STAGE_BASE;
    int tid = threadIdx.x;

    const __half* wh = g_gup_h + (size_t)e * H * F2;

    g1_load(sb, 0, wh, m0, 0, n0g, tid);
    cp_commit();
    g1_load(sb, 1, wh, m0, BK, n0g, tid);
    cp_commit();

    float acc[4][4][4];
#pragma unroll
    for (int i = 0; i < 4; i++)
#pragma unroll
        for (int j = 0; j < 4; j++)
#pragma unroll
            for (int r = 0; r < 4; r++) acc[i][j][r] = 0.f;

    int lane = tid & 31, w = tid >> 5;
    int warpM = w >> 2, warpN = w & 3;          // 2M x 4N
    int p0 = warpN * 16, p1 = 64 + warpN * 16;  // gate / up halves

    const int NS = H / BK;  // 16
    for (int ki = 0; ki < NS; ki++) {
        cp_wait1();
        __syncthreads();
        if (ki + 2 < NS)
            g1_load(sb, (ki + 2) % 3, wh, m0, (ki + 2) * BK, n0g, tid);
        cp_commit();
        uint32_t stg = sb + (ki % 3) * STG;
#pragma unroll
        for (int k16 = 0; k16 < 4; k16++)
            compute_k16(stg, lane, warpM, p0, p1, k16, acc);
    }

    // epilogue: j=0,1 gate; j+2 up (same inter cols)
#pragma unroll
    for (int i = 0; i < 4; i++) {
        int r0 = warpM * 64 + i * 16 + (lane >> 2);
#pragma unroll
        for (int j = 0; j < 2; j++) {
            int col = n0g + warpN * 16 + j * 8 + (lane & 3) * 2;
#pragma unroll
            for (int hfa = 0; hfa < 2; hfa++) {
                int m = r0 + hfa * 8;
                if (m < rows) {
                    float g0 = acc[i][j][hfa * 2 + 0];
                    float g1 = acc[i][j][hfa * 2 + 1];
                    float u0 = acc[i][j + 2][hfa * 2 + 0];
                    float u1 = acc[i][j + 2][hfa * 2 + 1];
                    float v0 = g0 / (1.f + __expf(-g0)) * u0;
                    float v1 = g1 / (1.f + __expf(-g1)) * u1;
                    __half2 hv = __floats2half2_rn(v0, v1);
                    ((uint32_t*)g_inter)[((size_t)(m0 + m) * IE + col) >> 1] =
                        *(uint32_t*)&hv;
                }
            }
        }
    }
}

// ---------------- GEMM2 ----------------
__device__ __forceinline__ void g2_load(uint32_t sb, int s,
                                        const __half* wh,
                                        int m0, int k0, int n0, int tid) {
    uint32_t stg = sb + s * STG;
#pragma unroll
    for (int q = 0; q < 4; q++) {
        int t = tid + q * 256;
        int row = t >> 3, c = t & 7;
        int sr = m0 + row;
        if (sr > N_TOK - 1) sr = N_TOK - 1;
        cp16(stg + OFF_AH + row * A_ROWB + c * 16,
             g_inter + (size_t)sr * IE + k0 + c * 8);
        int kr = t >> 4, c2 = t & 15;
        cp16(stg + OFF_BH + kr * B_ROWB + c2 * 16,
             wh + (size_t)(k0 + kr) * H + n0 + c2 * 8);
    }
}

__global__ __launch_bounds__(256, 2) void k_gemm2_mma(float* __restrict__ out) {
    int t = blockIdx.x;
    if (t >= g_num_tiles) return;
    int e = g_tile_expert[t];
    int m0 = g_offsets[e] + g_tile_mstart[t];
    int rows = g_offsets[e + 1] - m0;
    if (rows > 128) rows = 128;
    int n0 = blockIdx.y * 128;

    extern __shared__ char smraw[];
    int* sRow = (int*)smraw;
    uint32_t sb = s2u(smraw) + STAGE_BASE;
    int tid = threadIdx.x;
    if (tid < 128) sRow[tid] = (tid < rows) ? g_sorted[m0 + tid] : -1;
    __syncthreads();

    const __half* wh = g_dwn_h + (size_t)e * IE * H;

    g2_load(sb, 0, wh, m0, 0, n0, tid);
    cp_commit();
    g2_load(sb, 1, wh, m0, BK, n0, tid);
    cp_commit();

    float acc[4][4][4];
#pragma unroll
    for (int i = 0; i < 4; i++)
#pragma unroll
        for (int j = 0; j < 4; j++)
#pragma unroll
            for (int r = 0; r < 4; r++) acc[i][j][r] = 0.f;

    int lane = tid & 31, w = tid >> 5;
    int warpM = w >> 2, warpN = w & 3;
    int p0 = warpN * 32, p1 = warpN * 32 + 16;

    const int NS = IE / BK;  // 8
    for (int ki = 0; ki < NS; ki++) {
        cp_wait1();
        __syncthreads();
        if (ki + 2 < NS) g2_load(sb, (ki + 2) % 3, wh, m0, (ki + 2) * BK, n0, tid);
        cp_commit();
        uint32_t stg = sb + (ki % 3) * STG;
#pragma unroll
        for (int k16 = 0; k16 < 4; k16++)
            compute_k16(stg, lane, warpM, p0, p1, k16, acc);
    }

#pragma unroll
    for (int i = 0; i < 4; i++) {
        int r0 = warpM * 64 + i * 16 + (lane >> 2);
#pragma unroll
        for (int hfa = 0; hfa < 2; hfa++) {
            int m = r0 + hfa * 8;
            if (m < rows) {
                int token = sRow[m];
                float* po = out + (size_t)token * H + n0;
#pragma unroll
                for (int j = 0; j < 4; j++) {
                    int col = warpN * 32 + j * 8 + (lane & 3) * 2;
                    *(float2*)(po + col) =
                        make_float2(acc[i][j][hfa * 2 + 0], acc[i][j][hfa * 2 + 1]);
                }
            }
        }
    }
}

// ---------------- launch ----------------
extern "C" void kernel_launch(void* const* d_in, const int* in_sizes, int n_in,
                              void* d_out, int out_size) {
    const float* hs  = (const float*)d_in[0];
    const int*   tok = (const int*)d_in[1];
    const float* mu  = (const float*)d_in[2];
    const float* gup = (const float*)d_in[3];
    const float* dwn = (const float*)d_in[4];
    const float* rw  = (const float*)d_in[5];
    float* out = (float*)d_out;
    (void)in_sizes; (void)n_in; (void)out_size;

    cudaFuncSetAttribute(k_gemm1_mma, cudaFuncAttributeMaxDynamicSharedMemorySize,
                         SMEM_TOT);
    cudaFuncSetAttribute(k_gemm2_mma, cudaFuncAttributeMaxDynamicSharedMemorySize,
                         SMEM_TOT);

    k_router<<<N_TOK / 8, 256>>>(mu, tok, rw);
    k_plan<<<1, 32>>>();
    k_scatter<<<N_TOK / 256, 256>>>();
    k_cvt3<<<(GUP4 + DWN4 + X4) / 1024, 256>>>(gup, dwn, hs);

    k_gemm1_mma<<<dim3(72, 8), 256, SMEM_TOT>>>();
    k_gemm2_mma<<<dim3(72, 8), 256, SMEM_TOT>>>(out);
}

// round 14
// speedup vs baseline: 1.1891x; 1.0226x over previous
#include <cuda_runtime.h>
#include <cuda_fp16.h>
#include <cstdint>

// ---------------- problem constants ----------------
#define N_TOK 8192
#define H     1024
#define E     8
#define IE    512
#define F2    1024
#define VOCAB 32000

// ---------------- scratch ----------------
__device__ int g_expert_ids[N_TOK];
__device__ int g_counts[E];      // zero-init; k_plan re-zeros after use
__device__ int g_cursor[E];
__device__ int g_offsets[E + 1];
__device__ int g_sorted[N_TOK];
__device__ int g_pos[N_TOK];     // token -> sorted position
__device__ int g_tile_expert[96];
__device__ int g_tile_mstart[96];
__device__ int g_num_tiles;

__device__ __half g_xs[(size_t)N_TOK * H];      // sorted order, fp16
__device__ __half g_gup_h[(size_t)E * H * F2];  // fp16 weights
__device__ __half g_dwn_h[(size_t)E * IE * H];
__device__ __half g_inter[(size_t)N_TOK * IE];  // sorted order, fp16

// ---------------- PTX helpers ----------------
__device__ __forceinline__ uint32_t s2u(const void* p) {
    uint32_t a;
    asm("{ .reg .u64 t; cvta.to.shared.u64 t, %1; cvt.u32.u64 %0, t; }"
        : "=r"(a) : "l"(p));
    return a;
}
// .cg: bypass L1 (L2-only) — keeps staging traffic off the contended L1 pipe
__device__ __forceinline__ void cp16(uint32_t dst, const void* src) {
    asm volatile("cp.async.cg.shared.global [%0], [%1], 16;"
                 :: "r"(dst), "l"(src) : "memory");
}
__device__ __forceinline__ void cp_commit() {
    asm volatile("cp.async.commit_group;" ::: "memory");
}
__device__ __forceinline__ void cp_wait1() {
    asm volatile("cp.async.wait_group 1;" ::: "memory");
}
__device__ __forceinline__ void ldmx4(uint32_t* r, uint32_t a) {
    asm volatile("ldmatrix.sync.aligned.m8n8.x4.shared.b16 {%0,%1,%2,%3}, [%4];"
                 : "=r"(r[0]), "=r"(r[1]), "=r"(r[2]), "=r"(r[3]) : "r"(a));
}
__device__ __forceinline__ void ldmx4t(uint32_t* r, uint32_t a) {
    asm volatile("ldmatrix.sync.aligned.m8n8.x4.trans.shared.b16 {%0,%1,%2,%3}, [%4];"
                 : "=r"(r[0]), "=r"(r[1]), "=r"(r[2]), "=r"(r[3]) : "r"(a));
}
__device__ __forceinline__ void mma16816(float* d, const uint32_t* a,
                                         const uint32_t* b) {
    asm volatile(
        "mma.sync.aligned.m16n8k16.row.col.f32.f16.f16.f32 "
        "{%0,%1,%2,%3}, {%4,%5,%6,%7}, {%8,%9}, {%0,%1,%2,%3};"
        : "+f"(d[0]), "+f"(d[1]), "+f"(d[2]), "+f"(d[3])
        : "r"(a[0]), "r"(a[1]), "r"(a[2]), "r"(a[3]), "r"(b[0]), "r"(b[1]));
}

// ---------------- smem layout (BK = 64) ----------------
#define BK     64
#define A_ROWB 144   // 64 fp16 (128B) + 16B pad
#define B_ROWB 272   // 128 fp16 (256B) + 16B pad
#define OFF_AH 0
#define OFF_BH 18432
#define STG    35840          // 18432 + 64*272
#define STAGE_BASE 512
#define SMEM_TOT (STAGE_BASE + 3 * STG)   // 108032 (x2 CTA = 216064 <= 228KB)

__device__ __forceinline__ uint32_t a_addr(uint32_t base, int lane, int mbase,
                                           int k16) {
    int row = mbase + (lane & 15);
    return base + row * A_ROWB + k16 * 32 + ((lane >> 4) << 4);
}
__device__ __forceinline__ uint32_t b_addr(uint32_t base, int lane, int nbase,
                                           int k16) {
    int krow = k16 * 16 + (lane & 15);
    return base + krow * B_ROWB + nbase * 2 + ((lane >> 4) << 4);
}

// warp tile 64x32: one k16 step = 6 ldmatrix.x4 + 16 HMMA
__device__ __forceinline__ void compute_k16(uint32_t stg, int lane, int warpM,
                                            int p0, int p1, int k16,
                                            float acc[4][4][4]) {
    uint32_t ah[4][4], bh[2][4];
#pragma unroll
    for (int i = 0; i < 4; i++)
        ldmx4(ah[i], a_addr(stg + OFF_AH, lane, warpM * 64 + i * 16, k16));
    ldmx4t(bh[0], b_addr(stg + OFF_BH, lane, p0, k16));
    ldmx4t(bh[1], b_addr(stg + OFF_BH, lane, p1, k16));
#pragma unroll
    for (int i = 0; i < 4; i++) {
#pragma unroll
        for (int j = 0; j < 4; j++)
            mma16816(acc[i][j], ah[i], &bh[j >> 1][(j & 1) * 2]);
    }
}

// ---------------- router (+ smem histogram, float4 loads) ------------------
__global__ void k_router(const float* __restrict__ mu, const int* __restrict__ tok,
                         const float* __restrict__ w) {
    __shared__ __align__(16) float ws[E * H];
    __shared__ int hist[E];
    int tid = threadIdx.x;
    if (tid < E) hist[tid] = 0;
    for (int i = tid; i < E * H / 4; i += 256)
        ((float4*)ws)[i] = ((const float4*)w)[i];
    __syncthreads();
    int warp = tid >> 5, lane = tid & 31;
    int n = blockIdx.x * 8 + warp;
    const float4* mrow4 = (const float4*)(mu + (size_t)n * H);
    float acc[E];
#pragma unroll
    for (int e = 0; e < E; e++) acc[e] = 0.f;
    for (int h4 = lane; h4 < H / 4; h4 += 32) {
        float4 m = mrow4[h4];
#pragma unroll
        for (int e = 0; e < E; e++) {
            float4 wv = *(const float4*)&ws[e * H + h4 * 4];
            acc[e] += m.x * wv.x + m.y * wv.y + m.z * wv.z + m.w * wv.w;
        }
    }
#pragma unroll
    for (int off = 16; off > 0; off >>= 1)
#pragma unroll
        for (int e = 0; e < E; e++)
            acc[e] += __shfl_down_sync(0xffffffffu, acc[e], off);
    if (lane == 0) {
        int id = tok[n];
        if (id < 0) id = 0;
        if (id >= VOCAB) id = VOCAB - 1;
        int base = id & (E - 1);
        float best = -1e30f;
        int be = 0;
#pragma unroll
        for (int e = 0; e < E; e++) {
            float v = acc[e] + (e == base ? 10.0f : 0.0f);
            if (v > best) { best = v; be = e; }
        }
        g_expert_ids[n] = be;
        atomicAdd(&hist[be], 1);
    }
    __syncthreads();
    if (tid < E && hist[tid] > 0) atomicAdd(&g_counts[tid], hist[tid]);
}

// ---------------- plan: prefix + tile table + cursor init -------------------
__global__ void k_plan() {
    if (threadIdx.x == 0) {
        int off = 0;
        for (int e = 0; e < E; e++) {
            g_offsets[e] = off;
            g_cursor[e] = off;
            off += g_counts[e];
        }
        g_offsets[E] = off;
        int tt = 0;
        for (int e = 0; e < E; e++) {
            int cnt = g_counts[e];
            for (int ms = 0; ms < cnt; ms += 128) {
                g_tile_expert[tt] = e;
                g_tile_mstart[tt] = ms;
                tt++;
            }
        }
        g_num_tiles = tt;
        for (int e = 0; e < E; e++) g_counts[e] = 0;  // clean for replay
    }
}

// ---------------- scatter (atomic; order-independent outputs) --------------
__global__ void k_scatter() {
    int n = blockIdx.x * 256 + threadIdx.x;
    if (n < N_TOK) {
        int e = g_expert_ids[n];
        int p = atomicAdd(&g_cursor[e], 1);
        g_sorted[p] = n;
        g_pos[n] = p;
    }
}

// fp32 -> fp16: gup + dwn + x(sorted via g_pos)
// Block-strided ILP: each block owns 1024 consecutive float4 units (one
// region — all sizes are multiples of 1024); thread q-offsets are coalesced.
#define GUP4 (E * H * F2 / 4)    // 2097152
#define DWN4 (E * IE * H / 4)    // 1048576
#define X4   (N_TOK * H / 4)     // 2097152
#define H4   (H / 4)             // 256
__global__ void k_cvt3(const float* __restrict__ gup,
                       const float* __restrict__ dwn,
                       const float* __restrict__ x) {
    int base = blockIdx.x * 1024;
    const float* in;
    __half* out;
    int rbase;
    bool isx = false;
    if (base < GUP4) { in = gup; out = g_gup_h; rbase = base; }
    else if (base < GUP4 + DWN4) { in = dwn; out = g_dwn_h; rbase = base - GUP4; }
    else { in = x; out = g_xs; rbase = base - GUP4 - DWN4; isx = true; }
    int tid = threadIdx.x;
#pragma unroll
    for (int q = 0; q < 4; q++) {
        int iidx = rbase + q * 256 + tid;
        int oidx = iidx;
        if (isx) {
            int n = iidx >> 8;            // H4 = 256
            int c4 = iidx & 255;
            oidx = g_pos[n] * H4 + c4;    // g_pos[n] uniform per (block,q)
        }
        float4 v = ((const float4*)in)[iidx];
        __half2 a = __floats2half2_rn(v.x, v.y);
        __half2 b = __floats2half2_rn(v.z, v.w);
        ((uint2*)out)[oidx] = make_uint2(*(uint32_t*)&a, *(uint32_t*)&b);
    }
}

// ---------------- GEMM1 stage load (256 threads, 8 cp16 each) --------------
__device__ __forceinline__ void g1_load(uint32_t sb, int s,
                                        const __half* wh,
                                        int m0, int k0, int n0g, int tid) {
    uint32_t stg = sb + s * STG;
#pragma unroll
    for (int q = 0; q < 4; q++) {
        int t = tid + q * 256;  // 0..1023
        int row = t >> 3, c = t & 7;
        int sr = m0 + row;
        if (sr > N_TOK - 1) sr = N_TOK - 1;
        cp16(stg + OFF_AH + row * A_ROWB + c * 16,
             g_xs + (size_t)sr * H + k0 + c * 8);
        int kr = t >> 4, c2 = t & 15;
        int col = (c2 < 8) ? (n0g + c2 * 8) : (IE + n0g + (c2 - 8) * 8);
        cp16(stg + OFF_BH + kr * B_ROWB + c2 * 16,
             wh + (size_t)(k0 + kr) * F2 + col);
    }
}

__global__ __launch_bounds__(256, 2) void k_gemm1_mma() {
    int t = blockIdx.x;
    if (t >= g_num_tiles) return;
    int e = g_tile_expert[t];
    int m0 = g_offsets[e] + g_tile_mstart[t];
    int rows = g_offsets[e + 1] - m0;
    if (rows > 128) rows = 128;
    int n0g = blockIdx.y * 64;

    extern __shared__ char smraw[];
    uint32_t sb = s2u(smraw) + STAGE_BASE;
    int tid = threadIdx.x;

    const __half* wh = g_gup_h + (size_t)e * H * F2;

    g1_load(sb, 0, wh, m0, 0, n0g, tid);
    cp_commit();
    g1_load(sb, 1, wh, m0, BK, n0g, tid);
    cp_commit();

    float acc[4][4][4];
#pragma unroll
    for (int i = 0; i < 4; i++)
#pragma unroll
        for (int j = 0; j < 4; j++)
#pragma unroll
            for (int r = 0; r < 4; r++) acc[i][j][r] = 0.f;

    int lane = tid & 31, w = tid >> 5;
    int warpM = w >> 2, warpN = w & 3;          // 2M x 4N
    int p0 = warpN * 16, p1 = 64 + warpN * 16;  // gate / up halves

    const int NS = H / BK;  // 16
    for (int ki = 0; ki < NS; ki++) {
        cp_wait1();
        __syncthreads();
        if (ki + 2 < NS)
            g1_load(sb, (ki + 2) % 3, wh, m0, (ki + 2) * BK, n0g, tid);
        cp_commit();
        uint32_t stg = sb + (ki % 3) * STG;
#pragma unroll
        for (int k16 = 0; k16 < 4; k16++)
            compute_k16(stg, lane, warpM, p0, p1, k16, acc);
    }

    // epilogue: j=0,1 gate; j+2 up (same inter cols)
#pragma unroll
    for (int i = 0; i < 4; i++) {
        int r0 = warpM * 64 + i * 16 + (lane >> 2);
#pragma unroll
        for (int j = 0; j < 2; j++) {
            int col = n0g + warpN * 16 + j * 8 + (lane & 3) * 2;
#pragma unroll
            for (int hfa = 0; hfa < 2; hfa++) {
                int m = r0 + hfa * 8;
                if (m < rows) {
                    float g0 = acc[i][j][hfa * 2 + 0];
                    float g1 = acc[i][j][hfa * 2 + 1];
                    float u0 = acc[i][j + 2][hfa * 2 + 0];
                    float u1 = acc[i][j + 2][hfa * 2 + 1];
                    float v0 = g0 / (1.f + __expf(-g0)) * u0;
                    float v1 = g1 / (1.f + __expf(-g1)) * u1;
                    __half2 hv = __floats2half2_rn(v0, v1);
                    ((uint32_t*)g_inter)[((size_t)(m0 + m) * IE + col) >> 1] =
                        *(uint32_t*)&hv;
                }
            }
        }
    }
}

// ---------------- GEMM2 ----------------
__device__ __forceinline__ void g2_load(uint32_t sb, int s,
                                        const __half* wh,
                                        int m0, int k0, int n0, int tid) {
    uint32_t stg = sb + s * STG;
#pragma unroll
    for (int q = 0; q < 4; q++) {
        int t = tid + q * 256;
        int row = t >> 3, c = t & 7;
        int sr = m0 + row;
        if (sr > N_TOK - 1) sr = N_TOK - 1;
        cp16(stg + OFF_AH + row * A_ROWB + c * 16,
             g_inter + (size_t)sr * IE + k0 + c * 8);
        int kr = t >> 4, c2 = t & 15;
        cp16(stg + OFF_BH + kr * B_ROWB + c2 * 16,
             wh + (size_t)(k0 + kr) * H + n0 + c2 * 8);
    }
}

__global__ __launch_bounds__(256, 2) void k_gemm2_mma(float* __restrict__ out) {
    int t = blockIdx.x;
    if (t >= g_num_tiles) return;
    int e = g_tile_expert[t];
    int m0 = g_offsets[e] + g_tile_mstart[t];
    int rows = g_offsets[e + 1] - m0;
    if (rows > 128) rows = 128;
    int n0 = blockIdx.y * 128;

    extern __shared__ char smraw[];
    int* sRow = (int*)smraw;
    uint32_t sb = s2u(smraw) + STAGE_BASE;
    int tid = threadIdx.x;
    if (tid < 128) sRow[tid] = (tid < rows) ? g_sorted[m0 + tid] : -1;
    __syncthreads();

    const __half* wh = g_dwn_h + (size_t)e * IE * H;

    g2_load(sb, 0, wh, m0, 0, n0, tid);
    cp_commit();
    g2_load(sb, 1, wh, m0, BK, n0, tid);
    cp_commit();

    float acc[4][4][4];
#pragma unroll
    for (int i = 0; i < 4; i++)
#pragma unroll
        for (int j = 0; j < 4; j++)
#pragma unroll
            for (int r = 0; r < 4; r++) acc[i][j][r] = 0.f;

    int lane = tid & 31, w = tid >> 5;
    int warpM = w >> 2, warpN = w & 3;
    int p0 = warpN * 32, p1 = warpN * 32 + 16;

    const int NS = IE / BK;  // 8
    for (int ki = 0; ki < NS; ki++) {
        cp_wait1();
        __syncthreads();
        if (ki + 2 < NS) g2_load(sb, (ki + 2) % 3, wh, m0, (ki + 2) * BK, n0, tid);
        cp_commit();
        uint32_t stg = sb + (ki % 3) * STG;
#pragma unroll
        for (int k16 = 0; k16 < 4; k16++)
            compute_k16(stg, lane, warpM, p0, p1, k16, acc);
    }

#pragma unroll
    for (int i = 0; i < 4; i++) {
        int r0 = warpM * 64 + i * 16 + (lane >> 2);
#pragma unroll
        for (int hfa = 0; hfa < 2; hfa++) {
            int m = r0 + hfa * 8;
            if (m < rows) {
                int token = sRow[m];
                float* po = out + (size_t)token * H + n0;
#pragma unroll
                for (int j = 0; j < 4; j++) {
                    int col = warpN * 32 + j * 8 + (lane & 3) * 2;
                    *(float2*)(po + col) =
                        make_float2(acc[i][j][hfa * 2 + 0], acc[i][j][hfa * 2 + 1]);
                }
            }
        }
    }
}

// ---------------- launch ----------------
extern "C" void kernel_launch(void* const* d_in, const int* in_sizes, int n_in,
                              void* d_out, int out_size) {
    const float* hs  = (const float*)d_in[0];
    const int*   tok = (const int*)d_in[1];
    const float* mu  = (const float*)d_in[2];
    const float* gup = (const float*)d_in[3];
    const float* dwn = (const float*)d_in[4];
    const float* rw  = (const float*)d_in[5];
    float* out = (float*)d_out;
    (void)in_sizes; (void)n_in; (void)out_size;

    cudaFuncSetAttribute(k_gemm1_mma, cudaFuncAttributeMaxDynamicSharedMemorySize,
                         SMEM_TOT);
    cudaFuncSetAttribute(k_gemm2_mma, cudaFuncAttributeMaxDynamicSharedMemorySize,
                         SMEM_TOT);

    k_router<<<N_TOK / 8, 256>>>(mu, tok, rw);
    k_plan<<<1, 32>>>();
    k_scatter<<<N_TOK / 256, 256>>>();
    k_cvt3<<<(GUP4 + DWN4 + X4) / 1024, 256>>>(gup, dwn, hs);

    k_gemm1_mma<<<dim3(72, 8), 256, SMEM_TOT>>>();
    k_gemm2_mma<<<dim3(72, 8), 256, SMEM_TOT>>>(out);
}

// round 15
// speedup vs baseline: 1.2111x; 1.0184x over previous
#include <cuda_runtime.h>
#include <cuda_fp16.h>
#include <cstdint>

// ---------------- problem constants ----------------
#define N_TOK 8192
#define H     1024
#define E     8
#define IE    512
#define F2    1024
#define VOCAB 32000

// ---------------- scratch ----------------
__device__ int g_expert_ids[N_TOK];
__device__ int g_counts[E];      // zero-init; k_plan re-zeros after use
__device__ int g_cursor[E];
__device__ int g_offsets[E + 1];
__device__ int g_sorted[N_TOK];
__device__ int g_pos[N_TOK];     // token -> sorted position
__device__ int g_tile_expert[96];
__device__ int g_tile_mstart[96];
__device__ int g_num_tiles;

__device__ __half g_xs[(size_t)N_TOK * H];      // sorted order, fp16
__device__ __half g_gup_h[(size_t)E * H * F2];  // fp16 weights
__device__ __half g_dwn_h[(size_t)E * IE * H];
__device__ __half g_inter[(size_t)N_TOK * IE];  // sorted order, fp16

// ---------------- PTX helpers ----------------
__device__ __forceinline__ uint32_t s2u(const void* p) {
    uint32_t a;
    asm("{ .reg .u64 t; cvta.to.shared.u64 t, %1; cvt.u32.u64 %0, t; }"
        : "=r"(a) : "l"(p));
    return a;
}
// .cg: bypass L1 (L2-only) — keeps staging traffic off the contended L1 pipe
__device__ __forceinline__ void cp16(uint32_t dst, const void* src) {
    asm volatile("cp.async.cg.shared.global [%0], [%1], 16;"
                 :: "r"(dst), "l"(src) : "memory");
}
__device__ __forceinline__ void cp_commit() {
    asm volatile("cp.async.commit_group;" ::: "memory");
}
__device__ __forceinline__ void cp_wait1() {
    asm volatile("cp.async.wait_group 1;" ::: "memory");
}
__device__ __forceinline__ void ldmx4(uint32_t* r, uint32_t a) {
    asm volatile("ldmatrix.sync.aligned.m8n8.x4.shared.b16 {%0,%1,%2,%3}, [%4];"
                 : "=r"(r[0]), "=r"(r[1]), "=r"(r[2]), "=r"(r[3]) : "r"(a));
}
__device__ __forceinline__ void ldmx4t(uint32_t* r, uint32_t a) {
    asm volatile("ldmatrix.sync.aligned.m8n8.x4.trans.shared.b16 {%0,%1,%2,%3}, [%4];"
                 : "=r"(r[0]), "=r"(r[1]), "=r"(r[2]), "=r"(r[3]) : "r"(a));
}
__device__ __forceinline__ void mma16816(float* d, const uint32_t* a,
                                         const uint32_t* b) {
    asm volatile(
        "mma.sync.aligned.m16n8k16.row.col.f32.f16.f16.f32 "
        "{%0,%1,%2,%3}, {%4,%5,%6,%7}, {%8,%9}, {%0,%1,%2,%3};"
        : "+f"(d[0]), "+f"(d[1]), "+f"(d[2]), "+f"(d[3])
        : "r"(a[0]), "r"(a[1]), "r"(a[2]), "r"(a[3]), "r"(b[0]), "r"(b[1]));
}

// ---------------- smem layout (BK = 64) ----------------
#define BK     64
#define A_ROWB 144   // 64 fp16 (128B) + 16B pad
#define B_ROWB 272   // 128 fp16 (256B) + 16B pad
#define OFF_AH 0
#define OFF_BH 18432
#define STG    35840          // 18432 + 64*272
#define STAGE_BASE 512
#define SMEM_TOT (STAGE_BASE + 3 * STG)   // 108032 (x2 CTA = 216064 <= 228KB)

__device__ __forceinline__ uint32_t a_addr(uint32_t base, int lane, int mbase,
                                           int k16) {
    int row = mbase + (lane & 15);
    return base + row * A_ROWB + k16 * 32 + ((lane >> 4) << 4);
}
__device__ __forceinline__ uint32_t b_addr(uint32_t base, int lane, int nbase,
                                           int k16) {
    int krow = k16 * 16 + (lane & 15);
    return base + krow * B_ROWB + nbase * 2 + ((lane >> 4) << 4);
}

// warp tile 64x32: one k16 step = 6 ldmatrix.x4 + 16 HMMA
__device__ __forceinline__ void compute_k16(uint32_t stg, int lane, int warpM,
                                            int p0, int p1, int k16,
                                            float acc[4][4][4]) {
    uint32_t ah[4][4], bh[2][4];
#pragma unroll
    for (int i = 0; i < 4; i++)
        ldmx4(ah[i], a_addr(stg + OFF_AH, lane, warpM * 64 + i * 16, k16));
    ldmx4t(bh[0], b_addr(stg + OFF_BH, lane, p0, k16));
    ldmx4t(bh[1], b_addr(stg + OFF_BH, lane, p1, k16));
#pragma unroll
    for (int i = 0; i < 4; i++) {
#pragma unroll
        for (int j = 0; j < 4; j++)
            mma16816(acc[i][j], ah[i], &bh[j >> 1][(j & 1) * 2]);
    }
}

// ---------------- fused prep: router (blocks<1024) + weight cvt ------------
#define GUP4 (E * H * F2 / 4)    // 2097152
#define DWN4 (E * IE * H / 4)    // 1048576
#define W4   (GUP4 + DWN4)       // 3145728
#define X4   (N_TOK * H / 4)     // 2097152
#define H4   (H / 4)             // 256
#define RTR_BLKS 1024
#define WCV_BLKS (W4 / 2048)     // 1536

__global__ void k_prep(const float* __restrict__ mu, const int* __restrict__ tok,
                       const float* __restrict__ w,
                       const float* __restrict__ gup,
                       const float* __restrict__ dwn) {
    int tid = threadIdx.x;
    if (blockIdx.x >= RTR_BLKS) {
        // -------- weight conversion: 2048 float4 units per block --------
        int base = (blockIdx.x - RTR_BLKS) * 2048;
#pragma unroll
        for (int q = 0; q < 8; q++) {
            int i = base + q * 256 + tid;
            const float* in;
            __half* out;
            int idx;
            if (i < GUP4) { in = gup; out = g_gup_h; idx = i; }
            else { in = dwn; out = g_dwn_h; idx = i - GUP4; }
            float4 v = ((const float4*)in)[idx];
            __half2 a = __floats2half2_rn(v.x, v.y);
            __half2 b = __floats2half2_rn(v.z, v.w);
            ((uint2*)out)[idx] = make_uint2(*(uint32_t*)&a, *(uint32_t*)&b);
        }
        return;
    }
    // -------- router --------
    __shared__ __align__(16) float ws[E * H];
    __shared__ int hist[E];
    if (tid < E) hist[tid] = 0;
    for (int i = tid; i < E * H / 4; i += 256)
        ((float4*)ws)[i] = ((const float4*)w)[i];
    __syncthreads();
    int warp = tid >> 5, lane = tid & 31;
    int n = blockIdx.x * 8 + warp;
    const float4* mrow4 = (const float4*)(mu + (size_t)n * H);
    float acc[E];
#pragma unroll
    for (int e = 0; e < E; e++) acc[e] = 0.f;
    for (int h4 = lane; h4 < H / 4; h4 += 32) {
        float4 m = mrow4[h4];
#pragma unroll
        for (int e = 0; e < E; e++) {
            float4 wv = *(const float4*)&ws[e * H + h4 * 4];
            acc[e] += m.x * wv.x + m.y * wv.y + m.z * wv.z + m.w * wv.w;
        }
    }
#pragma unroll
    for (int off = 16; off > 0; off >>= 1)
#pragma unroll
        for (int e = 0; e < E; e++)
            acc[e] += __shfl_down_sync(0xffffffffu, acc[e], off);
    if (lane == 0) {
        int id = tok[n];
        if (id < 0) id = 0;
        if (id >= VOCAB) id = VOCAB - 1;
        int base = id & (E - 1);
        float best = -1e30f;
        int be = 0;
#pragma unroll
        for (int e = 0; e < E; e++) {
            float v = acc[e] + (e == base ? 10.0f : 0.0f);
            if (v > best) { best = v; be = e; }
        }
        g_expert_ids[n] = be;
        atomicAdd(&hist[be], 1);
    }
    __syncthreads();
    if (tid < E && hist[tid] > 0) atomicAdd(&g_counts[tid], hist[tid]);
}

// ---------------- plan: prefix + tile table + cursor init -------------------
__global__ void k_plan() {
    if (threadIdx.x == 0) {
        int off = 0;
        for (int e = 0; e < E; e++) {
            g_offsets[e] = off;
            g_cursor[e] = off;
            off += g_counts[e];
        }
        g_offsets[E] = off;
        int tt = 0;
        for (int e = 0; e < E; e++) {
            int cnt = g_counts[e];
            for (int ms = 0; ms < cnt; ms += 128) {
                g_tile_expert[tt] = e;
                g_tile_mstart[tt] = ms;
                tt++;
            }
        }
        g_num_tiles = tt;
        for (int e = 0; e < E; e++) g_counts[e] = 0;  // clean for replay
    }
}

// ---------------- scatter (atomic; order-independent outputs) --------------
__global__ void k_scatter() {
    int n = blockIdx.x * 256 + threadIdx.x;
    if (n < N_TOK) {
        int e = g_expert_ids[n];
        int p = atomicAdd(&g_cursor[e], 1);
        g_sorted[p] = n;
        g_pos[n] = p;
    }
}

// x fp32 -> fp16 into sorted order; block-strided coalesced, q=4 ILP
__global__ void k_cvt_x(const float* __restrict__ x) {
    int rbase = blockIdx.x * 1024;
    int tid = threadIdx.x;
#pragma unroll
    for (int q = 0; q < 4; q++) {
        int iidx = rbase + q * 256 + tid;
        int n = iidx >> 8;                 // H4 = 256
        int c4 = iidx & 255;
        int oidx = g_pos[n] * H4 + c4;     // uniform per (block,q)
        float4 v = ((const float4*)x)[iidx];
        __half2 a = __floats2half2_rn(v.x, v.y);
        __half2 b = __floats2half2_rn(v.z, v.w);
        ((uint2*)g_xs)[oidx] = make_uint2(*(uint32_t*)&a, *(uint32_t*)&b);
    }
}

// ---------------- GEMM1 stage load (256 threads, 8 cp16 each) --------------
__device__ __forceinline__ void g1_load(uint32_t sb, int s,
                                        const __half* wh,
                                        int m0, int k0, int n0g, int tid) {
    uint32_t stg = sb + s * STG;
#pragma unroll
    for (int q = 0; q < 4; q++) {
        int t = tid + q * 256;  // 0..1023
        int row = t >> 3, c = t & 7;
        int sr = m0 + row;
        if (sr > N_TOK - 1) sr = N_TOK - 1;
        cp16(stg + OFF_AH + row * A_ROWB + c * 16,
             g_xs + (size_t)sr * H + k0 + c * 8);
        int kr = t >> 4, c2 = t & 15;
        int col = (c2 < 8) ? (n0g + c2 * 8) : (IE + n0g + (c2 - 8) * 8);
        cp16(stg + OFF_BH + kr * B_ROWB + c2 * 16,
             wh + (size_t)(k0 + kr) * F2 + col);
    }
}

__global__ __launch_bounds__(256, 2) void k_gemm1_mma() {
    int t = blockIdx.x;
    if (t >= g_num_tiles) return;
    int e = g_tile_expert[t];
    int m0 = g_offsets[e] + g_tile_mstart[t];
    int rows = g_offsets[e + 1] - m0;
    if (rows > 128) rows = 128;
    int n0g = blockIdx.y * 64;

    extern __shared__ char smraw[];
    uint32_t sb = s2u(smraw) + STAGE_BASE;
    int tid = threadIdx.x;

    const __half* wh = g_gup_h + (size_t)e * H * F2;

    g1_load(sb, 0, wh, m0, 0, n0g, tid);
    cp_commit();
    g1_load(sb, 1, wh, m0, BK, n0g, tid);
    cp_commit();

    float acc[4][4][4];
#pragma unroll
    for (int i = 0; i < 4; i++)
#pragma unroll
        for (int j = 0; j < 4; j++)
#pragma unroll
            for (int r = 0; r < 4; r++) acc[i][j][r] = 0.f;

    int lane = tid & 31, w = tid >> 5;
    int warpM = w >> 2, warpN = w & 3;          // 2M x 4N
    int p0 = warpN * 16, p1 = 64 + warpN * 16;  // gate / up halves

    const int NS = H / BK;  // 16
    for (int ki = 0; ki < NS; ki++) {
        cp_wait1();
        __syncthreads();
        if (ki + 2 < NS)
            g1_load(sb, (ki + 2) % 3, wh, m0, (ki + 2) * BK, n0g, tid);
        cp_commit();
        uint32_t stg = sb + (ki % 3) * STG;
#pragma unroll
        for (int k16 = 0; k16 < 4; k16++)
            compute_k16(stg, lane, warpM, p0, p1, k16, acc);
    }

    // epilogue: j=0,1 gate; j+2 up (same inter cols)
#pragma unroll
    for (int i = 0; i < 4; i++) {
        int r0 = warpM * 64 + i * 16 + (lane >> 2);
#pragma unroll
        for (int j = 0; j < 2; j++) {
            int col = n0g + warpN * 16 + j * 8 + (lane & 3) * 2;
#pragma unroll
            for (int hfa = 0; hfa < 2; hfa++) {
                int m = r0 + hfa * 8;
                if (m < rows) {
                    float g0 = acc[i][j][hfa * 2 + 0];
                    float g1 = acc[i][j][hfa * 2 + 1];
                    float u0 = acc[i][j + 2][hfa * 2 + 0];
                    float u1 = acc[i][j + 2][hfa * 2 + 1];
                    float v0 = g0 / (1.f + __expf(-g0)) * u0;
                    float v1 = g1 / (1.f + __expf(-g1)) * u1;
                    __half2 hv = __floats2half2_rn(v0, v1);
                    ((uint32_t*)g_inter)[((size_t)(m0 + m) * IE + col) >> 1] =
                        *(uint32_t*)&hv;
                }
            }
        }
    }
}

// ---------------- GEMM2 ----------------
__device__ __forceinline__ void g2_load(uint32_t sb, int s,
                                        const __half* wh,
                                        int m0, int k0, int n0, int tid) {
    uint32_t stg = sb + s * STG;
#pragma unroll
    for (int q = 0; q < 4; q++) {
        int t = tid + q * 256;
        int row = t >> 3, c = t & 7;
        int sr = m0 + row;
        if (sr > N_TOK - 1) sr = N_TOK - 1;
        cp16(stg + OFF_AH + row * A_ROWB + c * 16,
             g_inter + (size_t)sr * IE + k0 + c * 8);
        int kr = t >> 4, c2 = t & 15;
        cp16(stg + OFF_BH + kr * B_ROWB + c2 * 16,
             wh + (size_t)(k0 + kr) * H + n0 + c2 * 8);
    }
}

__global__ __launch_bounds__(256, 2) void k_gemm2_mma(float* __restrict__ out) {
    int t = blockIdx.x;
    if (t >= g_num_tiles) return;
    int e = g_tile_expert[t];
    int m0 = g_offsets[e] + g_tile_mstart[t];
    int rows = g_offsets[e + 1] - m0;
    if (rows > 128) rows = 128;
    int n0 = blockIdx.y * 128;

    extern __shared__ char smraw[];
    int* sRow = (int*)smraw;
    uint32_t sb = s2u(smraw) + STAGE_BASE;
    int tid = threadIdx.x;
    if (tid < 128) sRow[tid] = (tid < rows) ? g_sorted[m0 + tid] : -1;
    __syncthreads();

    const __half* wh = g_dwn_h + (size_t)e * IE * H;

    g2_load(sb, 0, wh, m0, 0, n0, tid);
    cp_commit();
    g2_load(sb, 1, wh, m0, BK, n0, tid);
    cp_commit();

    float acc[4][4][4];
#pragma unroll
    for (int i = 0; i < 4; i++)
#pragma unroll
        for (int j = 0; j < 4; j++)
#pragma unroll
            for (int r = 0; r < 4; r++) acc[i][j][r] = 0.f;

    int lane = tid & 31, w = tid >> 5;
    int warpM = w >> 2, warpN = w & 3;
    int p0 = warpN * 32, p1 = warpN * 32 + 16;

    const int NS = IE / BK;  // 8
    for (int ki = 0; ki < NS; ki++) {
        cp_wait1();
        __syncthreads();
        if (ki + 2 < NS) g2_load(sb, (ki + 2) % 3, wh, m0, (ki + 2) * BK, n0, tid);
        cp_commit();
        uint32_t stg = sb + (ki % 3) * STG;
#pragma unroll
        for (int k16 = 0; k16 < 4; k16++)
            compute_k16(stg, lane, warpM, p0, p1, k16, acc);
    }

#pragma unroll
    for (int i = 0; i < 4; i++) {
        int r0 = warpM * 64 + i * 16 + (lane >> 2);
#pragma unroll
        for (int hfa = 0; hfa < 2; hfa++) {
            int m = r0 + hfa * 8;
            if (m < rows) {
                int token = sRow[m];
                float* po = out + (size_t)token * H + n0;
#pragma unroll
                for (int j = 0; j < 4; j++) {
                    int col = warpN * 32 + j * 8 + (lane & 3) * 2;
                    *(float2*)(po + col) =
                        make_float2(acc[i][j][hfa * 2 + 0], acc[i][j][hfa * 2 + 1]);
                }
            }
        }
    }
}

// ---------------- launch ----------------
extern "C" void kernel_launch(void* const* d_in, const int* in_sizes, int n_in,
                              void* d_out, int out_size) {
    const float* hs  = (const float*)d_in[0];
    const int*   tok = (const int*)d_in[1];
    const float* mu  = (const float*)d_in[2];
    const float* gup = (const float*)d_in[3];
    const float* dwn = (const float*)d_in[4];
    const float* rw  = (const float*)d_in[5];
    float* out = (float*)d_out;
    (void)in_sizes; (void)n_in; (void)out_size;

    cudaFuncSetAttribute(k_gemm1_mma, cudaFuncAttributeMaxDynamicSharedMemorySize,
                         SMEM_TOT);
    cudaFuncSetAttribute(k_gemm2_mma, cudaFuncAttributeMaxDynamicSharedMemorySize,
                         SMEM_TOT);

    k_prep<<<RTR_BLKS + WCV_BLKS, 256>>>(mu, tok, rw, gup, dwn);
    k_plan<<<1, 32>>>();
    k_scatter<<<N_TOK / 256, 256>>>();
    k_cvt_x<<<X4 / 1024, 256>>>(hs);

    k_gemm1_mma<<<dim3(72, 8), 256, SMEM_TOT>>>();
    k_gemm2_mma<<<dim3(72, 8), 256, SMEM_TOT>>>(out);
}

// round 16
// speedup vs baseline: 1.2276x; 1.0136x over previous
#include <cuda_runtime.h>
#include <cuda_fp16.h>
#include <cstdint>

// ---------------- problem constants ----------------
#define N_TOK 8192
#define H     1024
#define E     8
#define IE    512
#define F2    1024
#define VOCAB 32000

// ---------------- scratch ----------------
__device__ int g_expert_ids[N_TOK];
__device__ int g_counts[E];      // zero-init; plan re-zeros after use
__device__ int g_cursor[E];
__device__ int g_offsets[E + 1];
__device__ int g_sorted[N_TOK];
__device__ int g_tile_expert[96];
__device__ int g_tile_mstart[96];
__device__ int g_num_tiles;
__device__ int g_done;           // last-block counter; reset each run

__device__ __half g_xs[(size_t)N_TOK * H];      // sorted order, fp16
__device__ __half g_gup_h[(size_t)E * H * F2];  // fp16 weights
__device__ __half g_dwn_h[(size_t)E * IE * H];
__device__ __half g_inter[(size_t)N_TOK * IE];  // sorted order, fp16

// ---------------- PTX helpers ----------------
__device__ __forceinline__ uint32_t s2u(const void* p) {
    uint32_t a;
    asm("{ .reg .u64 t; cvta.to.shared.u64 t, %1; cvt.u32.u64 %0, t; }"
        : "=r"(a) : "l"(p));
    return a;
}
// .cg: bypass L1 (L2-only) — keeps staging traffic off the contended L1 pipe
__device__ __forceinline__ void cp16(uint32_t dst, const void* src) {
    asm volatile("cp.async.cg.shared.global [%0], [%1], 16;"
                 :: "r"(dst), "l"(src) : "memory");
}
__device__ __forceinline__ void cp_commit() {
    asm volatile("cp.async.commit_group;" ::: "memory");
}
__device__ __forceinline__ void cp_wait1() {
    asm volatile("cp.async.wait_group 1;" ::: "memory");
}
__device__ __forceinline__ void ldmx4(uint32_t* r, uint32_t a) {
    asm volatile("ldmatrix.sync.aligned.m8n8.x4.shared.b16 {%0,%1,%2,%3}, [%4];"
                 : "=r"(r[0]), "=r"(r[1]), "=r"(r[2]), "=r"(r[3]) : "r"(a));
}
__device__ __forceinline__ void ldmx4t(uint32_t* r, uint32_t a) {
    asm volatile("ldmatrix.sync.aligned.m8n8.x4.trans.shared.b16 {%0,%1,%2,%3}, [%4];"
                 : "=r"(r[0]), "=r"(r[1]), "=r"(r[2]), "=r"(r[3]) : "r"(a));
}
__device__ __forceinline__ void mma16816(float* d, const uint32_t* a,
                                         const uint32_t* b) {
    asm volatile(
        "mma.sync.aligned.m16n8k16.row.col.f32.f16.f16.f32 "
        "{%0,%1,%2,%3}, {%4,%5,%6,%7}, {%8,%9}, {%0,%1,%2,%3};"
        : "+f"(d[0]), "+f"(d[1]), "+f"(d[2]), "+f"(d[3])
        : "r"(a[0]), "r"(a[1]), "r"(a[2]), "r"(a[3]), "r"(b[0]), "r"(b[1]));
}

// ---------------- smem layout (BK = 64) ----------------
#define BK     64
#define A_ROWB 144   // 64 fp16 (128B) + 16B pad
#define B_ROWB 272   // 128 fp16 (256B) + 16B pad
#define OFF_AH 0
#define OFF_BH 18432
#define STG    35840          // 18432 + 64*272
#define STAGE_BASE 512
#define SMEM_TOT (STAGE_BASE + 3 * STG)   // 108032 (x2 CTA = 216064 <= 228KB)

__device__ __forceinline__ uint32_t a_addr(uint32_t base, int lane, int mbase,
                                           int k16) {
    int row = mbase + (lane & 15);
    return base + row * A_ROWB + k16 * 32 + ((lane >> 4) << 4);
}
__device__ __forceinline__ uint32_t b_addr(uint32_t base, int lane, int nbase,
                                           int k16) {
    int krow = k16 * 16 + (lane & 15);
    return base + krow * B_ROWB + nbase * 2 + ((lane >> 4) << 4);
}

// warp tile 64x32: one k16 step = 6 ldmatrix.x4 + 16 HMMA
__device__ __forceinline__ void compute_k16(uint32_t stg, int lane, int warpM,
                                            int p0, int p1, int k16,
                                            float acc[4][4][4]) {
    uint32_t ah[4][4], bh[2][4];
#pragma unroll
    for (int i = 0; i < 4; i++)
        ldmx4(ah[i], a_addr(stg + OFF_AH, lane, warpM * 64 + i * 16, k16));
    ldmx4t(bh[0], b_addr(stg + OFF_BH, lane, p0, k16));
    ldmx4t(bh[1], b_addr(stg + OFF_BH, lane, p1, k16));
#pragma unroll
    for (int i = 0; i < 4; i++) {
#pragma unroll
        for (int j = 0; j < 4; j++)
            mma16816(acc[i][j], ah[i], &bh[j >> 1][(j & 1) * 2]);
    }
}

// ---------------- fused prep: router + weight cvt + last-block plan --------
#define GUP4 (E * H * F2 / 4)    // 2097152
#define DWN4 (E * IE * H / 4)    // 1048576
#define W4   (GUP4 + DWN4)       // 3145728
#define X4   (N_TOK * H / 4)     // 2097152
#define H4   (H / 4)             // 256
#define RTR_BLKS 1024
#define WCV_BLKS (W4 / 2048)     // 1536
#define PREP_BLKS (RTR_BLKS + WCV_BLKS)

__global__ void k_prep(const float* __restrict__ mu, const int* __restrict__ tok,
                       const float* __restrict__ w,
                       const float* __restrict__ gup,
                       const float* __restrict__ dwn) {
    int tid = threadIdx.x;
    if (blockIdx.x >= RTR_BLKS) {
        // -------- weight conversion: 2048 float4 units per block --------
        int base = (blockIdx.x - RTR_BLKS) * 2048;
#pragma unroll
        for (int q = 0; q < 8; q++) {
            int i = base + q * 256 + tid;
            const float* in;
            __half* out;
            int idx;
            if (i < GUP4) { in = gup; out = g_gup_h; idx = i; }
            else { in = dwn; out = g_dwn_h; idx = i - GUP4; }
            float4 v = ((const float4*)in)[idx];
            __half2 a = __floats2half2_rn(v.x, v.y);
            __half2 b = __floats2half2_rn(v.z, v.w);
            ((uint2*)out)[idx] = make_uint2(*(uint32_t*)&a, *(uint32_t*)&b);
        }
    } else {
        // -------- router --------
        __shared__ __align__(16) float ws[E * H];
        __shared__ int hist[E];
        if (tid < E) hist[tid] = 0;
        for (int i = tid; i < E * H / 4; i += 256)
            ((float4*)ws)[i] = ((const float4*)w)[i];
        __syncthreads();
        int warp = tid >> 5, lane = tid & 31;
        int n = blockIdx.x * 8 + warp;
        const float4* mrow4 = (const float4*)(mu + (size_t)n * H);
        float acc[E];
#pragma unroll
        for (int e = 0; e < E; e++) acc[e] = 0.f;
        for (int h4 = lane; h4 < H / 4; h4 += 32) {
            float4 m = mrow4[h4];
#pragma unroll
            for (int e = 0; e < E; e++) {
                float4 wv = *(const float4*)&ws[e * H + h4 * 4];
                acc[e] += m.x * wv.x + m.y * wv.y + m.z * wv.z + m.w * wv.w;
            }
        }
#pragma unroll
        for (int off = 16; off > 0; off >>= 1)
#pragma unroll
            for (int e = 0; e < E; e++)
                acc[e] += __shfl_down_sync(0xffffffffu, acc[e], off);
        if (lane == 0) {
            int id = tok[n];
            if (id < 0) id = 0;
            if (id >= VOCAB) id = VOCAB - 1;
            int base = id & (E - 1);
            float best = -1e30f;
            int be = 0;
#pragma unroll
            for (int e = 0; e < E; e++) {
                float v = acc[e] + (e == base ? 10.0f : 0.0f);
                if (v > best) { best = v; be = e; }
            }
            g_expert_ids[n] = be;
            atomicAdd(&hist[be], 1);
        }
        __syncthreads();
        if (tid < E && hist[tid] > 0) atomicAdd(&g_counts[tid], hist[tid]);
    }

    // -------- last finishing block runs the plan --------
    __syncthreads();
    if (tid == 0) {
        __threadfence();
        int d = atomicAdd(&g_done, 1);
        if (d == PREP_BLKS - 1) {
            g_done = 0;          // reset for next graph replay
            __threadfence();     // acquire all blocks' g_counts writes
            int off = 0;
            for (int e = 0; e < E; e++) {
                g_offsets[e] = off;
                g_cursor[e] = off;
                off += g_counts[e];
            }
            g_offsets[E] = off;
            int tt = 0;
            for (int e = 0; e < E; e++) {
                int cnt = g_counts[e];
                for (int ms = 0; ms < cnt; ms += 128) {
                    g_tile_expert[tt] = e;
                    g_tile_mstart[tt] = ms;
                    tt++;
                }
            }
            g_num_tiles = tt;
            for (int e = 0; e < E; e++) g_counts[e] = 0;  // clean for replay
        }
    }
}

// ---------------- fused scatter + x convert (4 tokens per block) -----------
__global__ void k_sg(const float* __restrict__ x) {
    __shared__ int sp[4];
    int t0 = blockIdx.x * 4;
    int tid = threadIdx.x;
    if (tid < 4) {
        int n = t0 + tid;
        int e = g_expert_ids[n];
        int p = atomicAdd(&g_cursor[e], 1);
        g_sorted[p] = n;
        sp[tid] = p;
    }
    __syncthreads();
#pragma unroll
    for (int q = 0; q < 4; q++) {
        int idx = q * 256 + tid;        // 0..1023 = 4 rows x 256 float4
        int row = idx >> 8;             // 0..3
        int c4 = idx & 255;
        float4 v = ((const float4*)x)[(size_t)(t0 + row) * H4 + c4];
        __half2 a = __floats2half2_rn(v.x, v.y);
        __half2 b = __floats2half2_rn(v.z, v.w);
        ((uint2*)g_xs)[(size_t)sp[row] * H4 + c4] =
            make_uint2(*(uint32_t*)&a, *(uint32_t*)&b);
    }
}

// ---------------- GEMM1 stage load (256 threads, 8 cp16 each) --------------
__device__ __forceinline__ void g1_load(uint32_t sb, int s,
                                        const __half* wh,
                                        int m0, int k0, int n0g, int tid) {
    uint32_t stg = sb + s * STG;
#pragma unroll
    for (int q = 0; q < 4; q++) {
        int t = tid + q * 256;  // 0..1023
        int row = t >> 3, c = t & 7;
        int sr = m0 + row;
        if (sr > N_TOK - 1) sr = N_TOK - 1;
        cp16(stg + OFF_AH + row * A_ROWB + c * 16,
             g_xs + (size_t)sr * H + k0 + c * 8);
        int kr = t >> 4, c2 = t & 15;
        int col = (c2 < 8) ? (n0g + c2 * 8) : (IE + n0g + (c2 - 8) * 8);
        cp16(stg + OFF_BH + kr * B_ROWB + c2 * 16,
             wh + (size_t)(k0 + kr) * F2 + col);
    }
}

__global__ __launch_bounds__(256, 2) void k_gemm1_mma() {
    int t = blockIdx.x;
    if (t >= g_num_tiles) return;
    int e = g_tile_expert[t];
    int m0 = g_offsets[e] + g_tile_mstart[t];
    int rows = g_offsets[e + 1] - m0;
    if (rows > 128) rows = 128;
    int n0g = blockIdx.y * 64;

    extern __shared__ char smraw[];
    uint32_t sb = s2u(smraw) + STAGE_BASE;
    int tid = threadIdx.x;

    const __half* wh = g_gup_h + (size_t)e * H * F2;

    g1_load(sb, 0, wh, m0, 0, n0g, tid);
    cp_commit();
    g1_load(sb, 1, wh, m0, BK, n0g, tid);
    cp_commit();

    float acc[4][4][4];
#pragma unroll
    for (int i = 0; i < 4; i++)
#pragma unroll
        for (int j = 0; j < 4; j++)
#pragma unroll
            for (int r = 0; r < 4; r++) acc[i][j][r] = 0.f;

    int lane = tid & 31, w = tid >> 5;
    int warpM = w >> 2, warpN = w & 3;          // 2M x 4N
    int p0 = warpN * 16, p1 = 64 + warpN * 16;  // gate / up halves

    const int NS = H / BK;  // 16
    for (int ki = 0; ki < NS; ki++) {
        cp_wait1();
        __syncthreads();
        if (ki + 2 < NS)
            g1_load(sb, (ki + 2) % 3, wh, m0, (ki + 2) * BK, n0g, tid);
        cp_commit();
        uint32_t stg = sb + (ki % 3) * STG;
#pragma unroll
        for (int k16 = 0; k16 < 4; k16++)
            compute_k16(stg, lane, warpM, p0, p1, k16, acc);
    }

    // epilogue: j=0,1 gate; j+2 up (same inter cols)
#pragma unroll
    for (int i = 0; i < 4; i++) {
        int r0 = warpM * 64 + i * 16 + (lane >> 2);
#pragma unroll
        for (int j = 0; j < 2; j++) {
            int col = n0g + warpN * 16 + j * 8 + (lane & 3) * 2;
#pragma unroll
            for (int hfa = 0; hfa < 2; hfa++) {
                int m = r0 + hfa * 8;
                if (m < rows) {
                    float g0 = acc[i][j][hfa * 2 + 0];
                    float g1 = acc[i][j][hfa * 2 + 1];
                    float u0 = acc[i][j + 2][hfa * 2 + 0];
                    float u1 = acc[i][j + 2][hfa * 2 + 1];
                    float v0 = g0 / (1.f + __expf(-g0)) * u0;
                    float v1 = g1 / (1.f + __expf(-g1)) * u1;
                    __half2 hv = __floats2half2_rn(v0, v1);
                    ((uint32_t*)g_inter)[((size_t)(m0 + m) * IE + col) >> 1] =
                        *(uint32_t*)&hv;
                }
            }
        }
    }
}

// ---------------- GEMM2 ----------------
__device__ __forceinline__ void g2_load(uint32_t sb, int s,
                                        const __half* wh,
                                        int m0, int k0, int n0, int tid) {
    uint32_t stg = sb + s * STG;
#pragma unroll
    for (int q = 0; q < 4; q++) {
        int t = tid + q * 256;
        int row = t >> 3, c = t & 7;
        int sr = m0 + row;
        if (sr > N_TOK - 1) sr = N_TOK - 1;
        cp16(stg + OFF_AH + row * A_ROWB + c * 16,
             g_inter + (size_t)sr * IE + k0 + c * 8);
        int kr = t >> 4, c2 = t & 15;
        cp16(stg + OFF_BH + kr * B_ROWB + c2 * 16,
             wh + (size_t)(k0 + kr) * H + n0 + c2 * 8);
    }
}

__global__ __launch_bounds__(256, 2) void k_gemm2_mma(float* __restrict__ out) {
    int t = blockIdx.x;
    if (t >= g_num_tiles) return;
    int e = g_tile_expert[t];
    int m0 = g_offsets[e] + g_tile_mstart[t];
    int rows = g_offsets[e + 1] - m0;
    if (rows > 128) rows = 128;
    int n0 = blockIdx.y * 128;

    extern __shared__ char smraw[];
    int* sRow = (int*)smraw;
    uint32_t sb = s2u(smraw) + STAGE_BASE;
    int tid = threadIdx.x;
    if (tid < 128) sRow[tid] = (tid < rows) ? g_sorted[m0 + tid] : -1;
    __syncthreads();

    const __half* wh = g_dwn_h + (size_t)e * IE * H;

    g2_load(sb, 0, wh, m0, 0, n0, tid);
    cp_commit();
    g2_load(sb, 1, wh, m0, BK, n0, tid);
    cp_commit();

    float acc[4][4][4];
#pragma unroll
    for (int i = 0; i < 4; i++)
#pragma unroll
        for (int j = 0; j < 4; j++)
#pragma unroll
            for (int r = 0; r < 4; r++) acc[i][j][r] = 0.f;

    int lane = tid & 31, w = tid >> 5;
    int warpM = w >> 2, warpN = w & 3;
    int p0 = warpN * 32, p1 = warpN * 32 + 16;

    const int NS = IE / BK;  // 8
    for (int ki = 0; ki < NS; ki++) {
        cp_wait1();
        __syncthreads();
        if (ki + 2 < NS) g2_load(sb, (ki + 2) % 3, wh, m0, (ki + 2) * BK, n0, tid);
        cp_commit();
        uint32_t stg = sb + (ki % 3) * STG;
#pragma unroll
        for (int k16 = 0; k16 < 4; k16++)
            compute_k16(stg, lane, warpM, p0, p1, k16, acc);
    }

#pragma unroll
    for (int i = 0; i < 4; i++) {
        int r0 = warpM * 64 + i * 16 + (lane >> 2);
#pragma unroll
        for (int hfa = 0; hfa < 2; hfa++) {
            int m = r0 + hfa * 8;
            if (m < rows) {
                int token = sRow[m];
                float* po = out + (size_t)token * H + n0;
#pragma unroll
                for (int j = 0; j < 4; j++) {
                    int col = warpN * 32 + j * 8 + (lane & 3) * 2;
                    *(float2*)(po + col) =
                        make_float2(acc[i][j][hfa * 2 + 0], acc[i][j][hfa * 2 + 1]);
                }
            }
        }
    }
}

// ---------------- launch ----------------
extern "C" void kernel_launch(void* const* d_in, const int* in_sizes, int n_in,
                              void* d_out, int out_size) {
    const float* hs  = (const float*)d_in[0];
    const int*   tok = (const int*)d_in[1];
    const float* mu  = (const float*)d_in[2];
    const float* gup = (const float*)d_in[3];
    const float* dwn = (const float*)d_in[4];
    const float* rw  = (const float*)d_in[5];
    float* out = (float*)d_out;
    (void)in_sizes; (void)n_in; (void)out_size;

    cudaFuncSetAttribute(k_gemm1_mma, cudaFuncAttributeMaxDynamicSharedMemorySize,
                         SMEM_TOT);
    cudaFuncSetAttribute(k_gemm2_mma, cudaFuncAttributeMaxDynamicSharedMemorySize,
                         SMEM_TOT);

    k_prep<<<PREP_BLKS, 256>>>(mu, tok, rw, gup, dwn);
    k_sg<<<N_TOK / 4, 256>>>(hs);
    k_gemm1_mma<<<dim3(72, 8), 256, SMEM_TOT>>>();
    k_gemm2_mma<<<dim3(72, 8), 256, SMEM_TOT>>>(out);
}